// round 1
// baseline (speedup 1.0000x reference)
#include <cuda_runtime.h>
#include <math.h>

#define Bb   8
#define Cc   512
#define Nn   4096
#define NHh  8
#define Dd   64
#define EPSf 1e-5f

// ---------------- scratch (device globals; no allocation) ----------------
__device__ float g_qn [Bb*Cc*Nn];        // layernormed q, (B,C,N)
__device__ float g_kvn[Bb*Cc*Nn];        // layernormed kv, (B,C,N)
__device__ float g_Q  [Bb*NHh*Nn*Dd];    // (B,NH,N,D), rope applied
__device__ float g_K  [Bb*NHh*Nn*Dd];    // (B,NH,N,D), rope applied
__device__ float g_V  [Bb*NHh*Nn*Dd];    // (B,NH,N,D)
__device__ float g_AO [Bb*Nn*Cc];        // attention out, token-major (B,N,C)
__device__ float g_sin[Nn*32];
__device__ float g_cos[Nn*32];
__device__ float g_bias[NHh*64*64];      // (NH, Ws, Ws)

// ---------------- layernorm over C, channel-major in/out ----------------
__global__ __launch_bounds__(128) void ln_kernel(const float* __restrict__ x,
                                                 const float* __restrict__ g,
                                                 const float* __restrict__ bt,
                                                 float* __restrict__ y)
{
    int idx = blockIdx.x * blockDim.x + threadIdx.x;   // 0..B*N-1
    int b = idx >> 12;
    int n = idx & 4095;
    const float* xp = x + (size_t)b*Cc*Nn + n;
    float s = 0.f, s2 = 0.f;
#pragma unroll 16
    for (int c = 0; c < Cc; c++) {
        float v = xp[(size_t)c*Nn];
        s += v; s2 = fmaf(v, v, s2);
    }
    float mu  = s * (1.f/Cc);
    float var = s2 * (1.f/Cc) - mu*mu;
    float inv = rsqrtf(var + EPSf);
    float* yp = y + (size_t)b*Cc*Nn + n;
#pragma unroll 16
    for (int c = 0; c < Cc; c++) {
        float v = xp[(size_t)c*Nn];
        yp[(size_t)c*Nn] = (v - mu) * inv * g[c] + bt[c];
    }
}

// ---------------- rope table (double precision for accuracy) ----------------
__global__ void rope_kernel()
{
    int i = blockIdx.x * blockDim.x + threadIdx.x;     // Nn*32
    int n = i >> 5, k = i & 31;
    double invf = exp((-2.0 * (double)k / 64.0) * log(10000.0));
    double ang  = (double)n * invf;
    g_sin[i] = (float)sin(ang);
    g_cos[i] = (float)cos(ang);
}

// ---------------- relative position bias table ----------------
__global__ void bias_kernel(const float* __restrict__ table)
{
    int i = blockIdx.x * blockDim.x + threadIdx.x;     // NH*4096
    int h  = i >> 12;
    int qi = (i >> 6) & 63, ki = i & 63;
    int dh = (qi >> 3) - (ki >> 3) + 7;
    int dw = (qi & 7)  - (ki & 7)  + 7;
    g_bias[i] = table[(dh * 15 + dw) * NHh + h];
}

// ---------------- GEMM (TN): Y[t,j] = sum_c A_T[c,t]*W[j,c] + bias[j] ----
// A is channel-major (B,C,N). Output to (B,NH,N,D), optional fused RoPE.
template<bool ROPE>
__global__ __launch_bounds__(256) void gemm_qkv(const float* __restrict__ A,
                                                const float* __restrict__ Wt,
                                                const float* __restrict__ bias,
                                                float* __restrict__ out)
{
    const int t0 = blockIdx.x * 128;
    const int b  = t0 >> 12;
    const int n0 = t0 & 4095;
    const int j0 = blockIdx.y * 128;
    const int tid = threadIdx.x;
    const int tx = tid & 15, ty = tid >> 4;

    __shared__ __align__(16) float As[2][8*128];
    __shared__ __align__(16) float Bs[2][8*129];

    const float* Ab = A + (size_t)b*Cc*Nn + n0;
    const int la_k = tid >> 5;          // 0..7
    const int la_m = (tid & 31) << 2;   // 0..124
    const int lb_j = tid >> 1;          // 0..127
    const int lb_k = (tid & 1) << 2;    // 0 or 4

    float acc[8][8];
#pragma unroll
    for (int i = 0; i < 8; i++)
#pragma unroll
        for (int j = 0; j < 8; j++) acc[i][j] = 0.f;

    float4 aR = *(const float4*)(Ab + (size_t)la_k*Nn + la_m);
    float4 bR = *(const float4*)(Wt + (size_t)(j0+lb_j)*Cc + lb_k);
    *(float4*)&As[0][la_k*128 + la_m] = aR;
    Bs[0][(lb_k+0)*129 + lb_j] = bR.x;
    Bs[0][(lb_k+1)*129 + lb_j] = bR.y;
    Bs[0][(lb_k+2)*129 + lb_j] = bR.z;
    Bs[0][(lb_k+3)*129 + lb_j] = bR.w;
    __syncthreads();

    for (int kt = 0; kt < 64; kt++) {
        const int cur = kt & 1;
        if (kt < 63) {
            int c0 = (kt + 1) * 8;
            aR = *(const float4*)(Ab + (size_t)(c0 + la_k)*Nn + la_m);
            bR = *(const float4*)(Wt + (size_t)(j0+lb_j)*Cc + c0 + lb_k);
        }
        const float* Asb = As[cur];
        const float* Bsb = Bs[cur];
#pragma unroll
        for (int k = 0; k < 8; k++) {
            float ar[8], br[8];
#pragma unroll
            for (int i = 0; i < 8; i++) ar[i] = Asb[k*128 + ty + 16*i];
#pragma unroll
            for (int j = 0; j < 8; j++) br[j] = Bsb[k*129 + tx + 16*j];
#pragma unroll
            for (int i = 0; i < 8; i++)
#pragma unroll
                for (int j = 0; j < 8; j++) acc[i][j] = fmaf(ar[i], br[j], acc[i][j]);
        }
        if (kt < 63) {
            const int nxt = cur ^ 1;
            *(float4*)&As[nxt][la_k*128 + la_m] = aR;
            Bs[nxt][(lb_k+0)*129 + lb_j] = bR.x;
            Bs[nxt][(lb_k+1)*129 + lb_j] = bR.y;
            Bs[nxt][(lb_k+2)*129 + lb_j] = bR.z;
            Bs[nxt][(lb_k+3)*129 + lb_j] = bR.w;
            __syncthreads();
        }
    }

#pragma unroll
    for (int i = 0; i < 8; i++) {
        int n = n0 + ty + 16*i;
#pragma unroll
        for (int j = 0; j < 8; j++) {
            int jj = j0 + tx + 16*j;
            float v = acc[i][j] + bias[jj];
            if (ROPE) {
                int d = jj & 63;
                int p = (n << 5) + (d >> 1);
                float sv = g_sin[p], cv = g_cos[p];
                float other = __shfl_xor_sync(0xffffffffu, v, 1);
                v = (tx & 1) ? fmaf(other, sv, v*cv)
                             : fmaf(-other, sv, v*cv);
            }
            out[(((size_t)b*NHh + (jj >> 6))*Nn + n)*Dd + (jj & 63)] = v;
        }
    }
}

// ---------------- GEMM (NT): out proj + bias + residual, writes (B,C,N) ----
__global__ __launch_bounds__(256) void gemm_o(const float* __restrict__ A,   // g_AO (B,N,C)
                                              const float* __restrict__ Wt,  // Wo (C,C)
                                              const float* __restrict__ bias,// bo
                                              const float* __restrict__ resid, // g_qn (B,C,N)
                                              float* __restrict__ out)       // (B,C,N)
{
    const int t0 = blockIdx.x * 128;
    const int b  = t0 >> 12;
    const int n0 = t0 & 4095;
    const int j0 = blockIdx.y * 128;
    const int tid = threadIdx.x;
    const int tx = tid & 15, ty = tid >> 4;

    __shared__ __align__(16) float As[2][8*129];
    __shared__ __align__(16) float Bs[2][8*129];

    const int lm = tid >> 1;          // 0..127
    const int lk = (tid & 1) << 2;    // 0 or 4

    float acc[8][8];
#pragma unroll
    for (int i = 0; i < 8; i++)
#pragma unroll
        for (int j = 0; j < 8; j++) acc[i][j] = 0.f;

    float4 aR = *(const float4*)(A  + (size_t)(t0+lm)*Cc + lk);
    float4 bR = *(const float4*)(Wt + (size_t)(j0+lm)*Cc + lk);
    As[0][(lk+0)*129 + lm] = aR.x;  As[0][(lk+1)*129 + lm] = aR.y;
    As[0][(lk+2)*129 + lm] = aR.z;  As[0][(lk+3)*129 + lm] = aR.w;
    Bs[0][(lk+0)*129 + lm] = bR.x;  Bs[0][(lk+1)*129 + lm] = bR.y;
    Bs[0][(lk+2)*129 + lm] = bR.z;  Bs[0][(lk+3)*129 + lm] = bR.w;
    __syncthreads();

    for (int kt = 0; kt < 64; kt++) {
        const int cur = kt & 1;
        if (kt < 63) {
            int c0 = (kt + 1) * 8;
            aR = *(const float4*)(A  + (size_t)(t0+lm)*Cc + c0 + lk);
            bR = *(const float4*)(Wt + (size_t)(j0+lm)*Cc + c0 + lk);
        }
        const float* Asb = As[cur];
        const float* Bsb = Bs[cur];
#pragma unroll
        for (int k = 0; k < 8; k++) {
            float ar[8], br[8];
#pragma unroll
            for (int i = 0; i < 8; i++) ar[i] = Asb[k*129 + tx + 16*i];
#pragma unroll
            for (int j = 0; j < 8; j++) br[j] = Bsb[k*129 + ty + 16*j];
#pragma unroll
            for (int i = 0; i < 8; i++)
#pragma unroll
                for (int j = 0; j < 8; j++) acc[i][j] = fmaf(ar[i], br[j], acc[i][j]);
        }
        if (kt < 63) {
            const int nxt = cur ^ 1;
            As[nxt][(lk+0)*129 + lm] = aR.x;  As[nxt][(lk+1)*129 + lm] = aR.y;
            As[nxt][(lk+2)*129 + lm] = aR.z;  As[nxt][(lk+3)*129 + lm] = aR.w;
            Bs[nxt][(lk+0)*129 + lm] = bR.x;  Bs[nxt][(lk+1)*129 + lm] = bR.y;
            Bs[nxt][(lk+2)*129 + lm] = bR.z;  Bs[nxt][(lk+3)*129 + lm] = bR.w;
            __syncthreads();
        }
    }

#pragma unroll
    for (int j = 0; j < 8; j++) {
        int jj = j0 + ty + 16*j;
        float bj = bias[jj];
        size_t rowbase = ((size_t)b*Cc + jj)*Nn;
#pragma unroll
        for (int i = 0; i < 8; i++) {
            int n = n0 + tx + 16*i;
            size_t o = rowbase + n;
            out[o] = acc[i][j] + bj + resid[o];
        }
    }
}

// ---------------- windowed attention: one block per (head, window) ----------
__global__ __launch_bounds__(256) void attn_kernel()
{
    __shared__ __align__(16) float Qs[4096];   // Q^T (d-major, swizzled); later aliased as P
    __shared__ __align__(16) float Ks[4096];   // K^T (d-major, swizzled)
    __shared__ __align__(16) float Vs[4096];   // V   (k-major)

    const int bx  = blockIdx.x;     // 0..4095
    const int h   = bx >> 9;
    const int win = bx & 511;
    const int b   = win >> 6;
    const int w   = win & 63;
    const int wy  = w >> 3, wx = w & 7;
    const int tid = threadIdx.x;

    const int tok0 = tid >> 4;              // 0..15
    const int d4   = (tid & 15) << 2;       // 0..60
    const size_t baseQK = ((size_t)b*NHh + h)*Nn*Dd;
    const int sw = ((d4 >> 2) & 15) << 2;
#pragma unroll
    for (int r = 0; r < 4; r++) {
        int t = tok0 + 16*r;
        int n = ((wy << 3) + (t >> 3))*64 + (wx << 3) + (t & 7);
        const float4 q4 = *(const float4*)(g_Q + baseQK + (size_t)n*Dd + d4);
        const float4 k4 = *(const float4*)(g_K + baseQK + (size_t)n*Dd + d4);
        const float4 v4 = *(const float4*)(g_V + baseQK + (size_t)n*Dd + d4);
        int ts = t ^ sw;
        Qs[(d4+0)*64 + ts] = q4.x;  Qs[(d4+1)*64 + ts] = q4.y;
        Qs[(d4+2)*64 + ts] = q4.z;  Qs[(d4+3)*64 + ts] = q4.w;
        Ks[(d4+0)*64 + ts] = k4.x;  Ks[(d4+1)*64 + ts] = k4.y;
        Ks[(d4+2)*64 + ts] = k4.z;  Ks[(d4+3)*64 + ts] = k4.w;
        *(float4*)&Vs[t*64 + d4] = v4;
    }
    __syncthreads();

    const int tx = tid & 15, ty = tid >> 4;
    float s[4][4];
#pragma unroll
    for (int i = 0; i < 4; i++)
#pragma unroll
        for (int j = 0; j < 4; j++) s[i][j] = 0.f;

#pragma unroll 4
    for (int d = 0; d < 64; d++) {
        int swd = ((d >> 2) & 15) << 2;
        float qr[4], kr[4];
#pragma unroll
        for (int i = 0; i < 4; i++) qr[i] = Qs[d*64 + ((ty + 16*i) ^ swd)];
#pragma unroll
        for (int j = 0; j < 4; j++) kr[j] = Ks[d*64 + ((tx + 16*j) ^ swd)];
#pragma unroll
        for (int i = 0; i < 4; i++)
#pragma unroll
            for (int j = 0; j < 4; j++) s[i][j] = fmaf(qr[i], kr[j], s[i][j]);
    }
    __syncthreads();   // everyone done reading Qs before it becomes P

    const float* bh = g_bias + (h << 12);
    float* Ps = Qs;
#pragma unroll
    for (int i = 0; i < 4; i++) {
        int qi = ty + 16*i;
        float m = -1e30f;
#pragma unroll
        for (int j = 0; j < 4; j++) {
            float v = fmaf(s[i][j], 0.125f, bh[qi*64 + tx + 16*j]);
            s[i][j] = v;
            m = fmaxf(m, v);
        }
#pragma unroll
        for (int off = 8; off; off >>= 1)
            m = fmaxf(m, __shfl_xor_sync(0xffffffffu, m, off));
        float sum = 0.f;
#pragma unroll
        for (int j = 0; j < 4; j++) {
            float e = expf(s[i][j] - m);
            s[i][j] = e;
            sum += e;
        }
#pragma unroll
        for (int off = 8; off; off >>= 1)
            sum += __shfl_xor_sync(0xffffffffu, sum, off);
        float inv = 1.f / sum;
#pragma unroll
        for (int j = 0; j < 4; j++)
            Ps[qi*64 + tx + 16*j] = s[i][j] * inv;
    }
    __syncthreads();

    float o[4][4];
#pragma unroll
    for (int i = 0; i < 4; i++)
#pragma unroll
        for (int j = 0; j < 4; j++) o[i][j] = 0.f;

#pragma unroll 4
    for (int k = 0; k < 64; k++) {
        float pr[4], vr[4];
#pragma unroll
        for (int i = 0; i < 4; i++) pr[i] = Ps[(ty + 16*i)*64 + k];
#pragma unroll
        for (int j = 0; j < 4; j++) vr[j] = Vs[k*64 + tx + 16*j];
#pragma unroll
        for (int i = 0; i < 4; i++)
#pragma unroll
            for (int j = 0; j < 4; j++) o[i][j] = fmaf(pr[i], vr[j], o[i][j]);
    }

#pragma unroll
    for (int i = 0; i < 4; i++) {
        int t = ty + 16*i;
        int n = ((wy << 3) + (t >> 3))*64 + (wx << 3) + (t & 7);
        size_t base = ((size_t)b*Nn + n)*Cc + (h << 6);
#pragma unroll
        for (int j = 0; j < 4; j++)
            g_AO[base + tx + 16*j] = o[i][j];
    }
}

// ---------------- host side ----------------
extern "C" void kernel_launch(void* const* d_in, const int* in_sizes, int n_in,
                              void* d_out, int out_size)
{
    const float* q    = (const float*)d_in[0];
    const float* kv   = (const float*)d_in[1];
    const float* gq   = (const float*)d_in[2];
    const float* bqln = (const float*)d_in[3];
    const float* gkv  = (const float*)d_in[4];
    const float* bkvln= (const float*)d_in[5];
    const float* Wq   = (const float*)d_in[6];
    const float* bq   = (const float*)d_in[7];
    const float* Wk   = (const float*)d_in[8];
    const float* bk   = (const float*)d_in[9];
    const float* Wv   = (const float*)d_in[10];
    const float* bv   = (const float*)d_in[11];
    const float* Wo   = (const float*)d_in[12];
    const float* bo   = (const float*)d_in[13];
    const float* tbl  = (const float*)d_in[14];
    float* out = (float*)d_out;

    void* p;
    cudaGetSymbolAddress(&p, g_qn);  float* qn  = (float*)p;
    cudaGetSymbolAddress(&p, g_kvn); float* kvn = (float*)p;
    cudaGetSymbolAddress(&p, g_Q);   float* Qb  = (float*)p;
    cudaGetSymbolAddress(&p, g_K);   float* Kb  = (float*)p;
    cudaGetSymbolAddress(&p, g_V);   float* Vb  = (float*)p;
    cudaGetSymbolAddress(&p, g_AO);  float* AO  = (float*)p;

    // layernorms (channel-major in and out)
    ln_kernel<<<256, 128>>>(q,  gq,  bqln,  qn);
    ln_kernel<<<256, 128>>>(kv, gkv, bkvln, kvn);

    // rope + bias tables
    rope_kernel<<<(Nn*32)/256, 256>>>();
    bias_kernel<<<(NHh*64*64)/256, 256>>>(tbl);

    // projections (rope fused for Q and K)
    dim3 gg(256, 4);
    gemm_qkv<true ><<<gg, 256>>>(qn,  Wq, bq, Qb);
    gemm_qkv<true ><<<gg, 256>>>(kvn, Wk, bk, Kb);
    gemm_qkv<false><<<gg, 256>>>(kvn, Wv, bv, Vb);

    // windowed attention
    attn_kernel<<<NHh * Bb * 64, 256>>>();

    // output projection + bias + residual, straight into (B,C,H,W)
    gemm_o<<<gg, 256>>>(AO, Wo, bo, qn, out);
}

// round 2
// speedup vs baseline: 2.5514x; 2.5514x over previous
#include <cuda_runtime.h>
#include <math.h>

#define Bb   8
#define Cc   512
#define Nn   4096
#define NHh  8
#define Dd   64
#define EPSf 1e-5f

// ---------------- scratch (device globals; no allocation) ----------------
__device__ float g_qn [Bb*Cc*Nn];        // layernormed q, (B,C,N)
__device__ float g_kvn[Bb*Cc*Nn];        // layernormed kv, (B,C,N)
__device__ float g_Q  [Bb*NHh*Nn*Dd];    // (B,NH,N,D), rope applied
__device__ float g_K  [Bb*NHh*Nn*Dd];
__device__ float g_V  [Bb*NHh*Nn*Dd];
__device__ float g_AO [Bb*Nn*Cc];        // attention out, token-major (B,N,C)
__device__ float g_sin[Nn*32];
__device__ float g_cos[Nn*32];
__device__ float g_bias[NHh*64*64];      // (NH, Ws, Ws)

// ---------------- small helpers ----------------
__device__ __forceinline__ unsigned f2tf(float x) {
    unsigned r; asm("cvt.rna.tf32.f32 %0, %1;" : "=r"(r) : "f"(x)); return r;
}
__device__ __forceinline__ unsigned sptr(const void* p) {
    return (unsigned)__cvta_generic_to_shared(p);
}
#define CP16(d, s)  asm volatile("cp.async.cg.shared.global [%0], [%1], 16;" :: "r"(d), "l"(s))
#define CP_COMMIT() asm volatile("cp.async.commit_group;")
#define CP_WAIT(n)  asm volatile("cp.async.wait_group %0;" :: "n"(n))

__device__ __forceinline__ void mma_tf32(float* c, const unsigned* a, const unsigned* b) {
    asm volatile(
        "mma.sync.aligned.m16n8k8.row.col.f32.tf32.tf32.f32 "
        "{%0,%1,%2,%3}, {%4,%5,%6,%7}, {%8,%9}, {%0,%1,%2,%3};"
        : "+f"(c[0]), "+f"(c[1]), "+f"(c[2]), "+f"(c[3])
        : "r"(a[0]), "r"(a[1]), "r"(a[2]), "r"(a[3]), "r"(b[0]), "r"(b[1]));
}

// ---------------- layernorm over C, channel-major in/out ----------------
__global__ __launch_bounds__(128) void ln_kernel(const float* __restrict__ x,
                                                 const float* __restrict__ g,
                                                 const float* __restrict__ bt,
                                                 float* __restrict__ y)
{
    int idx = blockIdx.x * blockDim.x + threadIdx.x;   // 0..B*N-1
    int b = idx >> 12;
    int n = idx & 4095;
    const float* xp = x + (size_t)b*Cc*Nn + n;
    float s = 0.f, s2 = 0.f;
#pragma unroll 16
    for (int c = 0; c < Cc; c++) {
        float v = xp[(size_t)c*Nn];
        s += v; s2 = fmaf(v, v, s2);
    }
    float mu  = s * (1.f/Cc);
    float var = s2 * (1.f/Cc) - mu*mu;
    float inv = rsqrtf(var + EPSf);
    float* yp = y + (size_t)b*Cc*Nn + n;
#pragma unroll 16
    for (int c = 0; c < Cc; c++) {
        float v = xp[(size_t)c*Nn];
        yp[(size_t)c*Nn] = (v - mu) * inv * g[c] + bt[c];
    }
}

// ---------------- rope table (double precision for accuracy) ----------------
__global__ void rope_kernel()
{
    int i = blockIdx.x * blockDim.x + threadIdx.x;     // Nn*32
    int n = i >> 5, k = i & 31;
    double invf = exp((-2.0 * (double)k / 64.0) * log(10000.0));
    double ang  = (double)n * invf;
    g_sin[i] = (float)sin(ang);
    g_cos[i] = (float)cos(ang);
}

// ---------------- relative position bias table ----------------
__global__ void bias_kernel(const float* __restrict__ table)
{
    int i = blockIdx.x * blockDim.x + threadIdx.x;     // NH*4096
    int h  = i >> 12;
    int qi = (i >> 6) & 63, ki = i & 63;
    int dh = (qi >> 3) - (ki >> 3) + 7;
    int dw = (qi & 7)  - (ki & 7)  + 7;
    g_bias[i] = table[(dh * 15 + dw) * NHh + h];
}

// ================= tf32 tensor-core GEMM: QKV projections ==================
// Y[t,j] = sum_c A_T[c,t] * Wt[j,c] + bias[j]; A channel-major (B,C,N).
// Output (B,NH,N,D) with optional fused RoPE.
// Block 128(m) x 128(n) x K=512, BK=32, 8 warps (2m x 4n), warp 64x32.
template<bool ROPE>
__global__ __launch_bounds__(256) void gemm_qkv_tc(const float* __restrict__ A,
                                                   const float* __restrict__ Wt,
                                                   const float* __restrict__ bias,
                                                   float* __restrict__ out)
{
    extern __shared__ float sm[];
    float* As = sm;              // [2][32][128], col swizzled by (k&3)<<3
    float* Bs = sm + 2*32*128;   // [2][128][36]

    const int t0 = blockIdx.x * 128;
    const int b  = t0 >> 12;
    const int n0 = t0 & 4095;
    const int j0 = blockIdx.y * 128;
    const int tid = threadIdx.x;
    const int lane = tid & 31, wid = tid >> 5;
    const int wm = wid & 1, wn = wid >> 1;
    const int r = lane >> 2, q = lane & 3;

    const float* Ab = A + (size_t)b*Cc*Nn + n0;

    float acc[4][4][4];
#pragma unroll
    for (int i = 0; i < 4; i++)
#pragma unroll
        for (int j = 0; j < 4; j++)
#pragma unroll
            for (int k = 0; k < 4; k++) acc[i][j][k] = 0.f;

    // ---- stage loader ----
    const int la_k  = tid >> 5;            // 0..7 (A row within pass)
    const int la_m4 = (tid & 31) << 2;     // 0..124
    const int lb_n  = tid >> 3;            // 0..31 (B row within pass)
    const int lb_k4 = (tid & 7) << 2;      // 0..28

#define LOAD_STAGE_QKV(S, BUF)                                                   \
    {                                                                            \
        float* Ad = As + (BUF)*4096;                                             \
        float* Bd = Bs + (BUF)*4608;                                             \
        int c0 = (S)*32;                                                         \
        _Pragma("unroll")                                                        \
        for (int p = 0; p < 4; p++) {                                            \
            int k = p*8 + la_k;                                                  \
            CP16(sptr(Ad + k*128 + (la_m4 ^ ((k&3)<<3))),                        \
                 Ab + (size_t)(c0+k)*Nn + la_m4);                                \
        }                                                                        \
        _Pragma("unroll")                                                        \
        for (int p = 0; p < 4; p++) {                                            \
            int n = p*32 + lb_n;                                                 \
            CP16(sptr(Bd + n*36 + lb_k4),                                        \
                 Wt + (size_t)(j0+n)*Cc + c0 + lb_k4);                           \
        }                                                                        \
    }

    LOAD_STAGE_QKV(0, 0); CP_COMMIT();

#pragma unroll 1
    for (int s = 0; s < 16; s++) {
        if (s < 15) { LOAD_STAGE_QKV(s+1, (s+1)&1); CP_COMMIT(); CP_WAIT(1); }
        else        { CP_WAIT(0); }
        __syncthreads();

        const float* Ac = As + (s&1)*4096;
        const float* Bc = Bs + (s&1)*4608;
#pragma unroll
        for (int kk = 0; kk < 4; kk++) {
            const int kb = kk*8;
            unsigned af[4][4], bf[4][2];
#pragma unroll
            for (int i = 0; i < 4; i++) {
                int m  = wm*64 + 16*i + r;
                int sw = q << 3;
                af[i][0] = f2tf(Ac[(kb+q)  *128 + ( m     ^ sw)]);
                af[i][1] = f2tf(Ac[(kb+q)  *128 + ((m+8)  ^ sw)]);
                af[i][2] = f2tf(Ac[(kb+4+q)*128 + ( m     ^ sw)]);
                af[i][3] = f2tf(Ac[(kb+4+q)*128 + ((m+8)  ^ sw)]);
            }
#pragma unroll
            for (int j = 0; j < 4; j++) {
                int n = wn*32 + 8*j + r;
                bf[j][0] = f2tf(Bc[n*36 + kb + q]);
                bf[j][1] = f2tf(Bc[n*36 + kb + 4 + q]);
            }
#pragma unroll
            for (int i = 0; i < 4; i++)
#pragma unroll
                for (int j = 0; j < 4; j++)
                    mma_tf32(acc[i][j], af[i], bf[j]);
        }
        __syncthreads();
    }
#undef LOAD_STAGE_QKV

    // ---- epilogue: bias (+ RoPE) ----
#pragma unroll
    for (int i = 0; i < 4; i++) {
        int n_base = n0 + wm*64 + 16*i + r;
#pragma unroll
        for (int j = 0; j < 4; j++) {
            int jj = j0 + wn*32 + 8*j + 2*q;
            int hh = jj >> 6;
            int d  = jj & 63;                     // even
            float bv0 = bias[jj], bv1 = bias[jj+1];
#pragma unroll
            for (int half = 0; half < 2; half++) {
                int n = n_base + 8*half;
                float v0 = acc[i][j][2*half+0] + bv0;
                float v1 = acc[i][j][2*half+1] + bv1;
                float2 st;
                if (ROPE) {
                    int p = (n << 5) + (d >> 1);
                    float sv = g_sin[p], cv = g_cos[p];
                    st.x = v0*cv - v1*sv;
                    st.y = v0*sv + v1*cv;
                } else {
                    st.x = v0; st.y = v1;
                }
                *(float2*)&out[(((size_t)b*NHh + hh)*Nn + n)*Dd + d] = st;
            }
        }
    }
}

// ================= tf32 tensor-core GEMM: output projection ================
// A = g_AO (B,N,C) row-major token x channel; Wt = Wo (C,C);
// out (B,C,N) = A @ Wo^T + bo + resid.
__global__ __launch_bounds__(256) void gemm_o_tc(const float* __restrict__ A,
                                                 const float* __restrict__ Wt,
                                                 const float* __restrict__ bias,
                                                 const float* __restrict__ resid,
                                                 float* __restrict__ out)
{
    extern __shared__ float sm[];
    float* As = sm;              // [2][128][36]  (m-major, k contiguous)
    float* Bs = sm + 2*128*36;   // [2][128][36]

    const int t0 = blockIdx.x * 128;
    const int b  = t0 >> 12;
    const int n0 = t0 & 4095;
    const int j0 = blockIdx.y * 128;
    const int tid = threadIdx.x;
    const int lane = tid & 31, wid = tid >> 5;
    const int wm = wid & 1, wn = wid >> 1;
    const int r = lane >> 2, q = lane & 3;

    float acc[4][4][4];
#pragma unroll
    for (int i = 0; i < 4; i++)
#pragma unroll
        for (int j = 0; j < 4; j++)
#pragma unroll
            for (int k = 0; k < 4; k++) acc[i][j][k] = 0.f;

    const int lr  = tid >> 3;            // 0..31
    const int lk4 = (tid & 7) << 2;      // 0..28

#define LOAD_STAGE_O(S, BUF)                                                     \
    {                                                                            \
        float* Ad = As + (BUF)*4608;                                             \
        float* Bd = Bs + (BUF)*4608;                                             \
        int c0 = (S)*32;                                                         \
        _Pragma("unroll")                                                        \
        for (int p = 0; p < 4; p++) {                                            \
            int m = p*32 + lr;                                                   \
            CP16(sptr(Ad + m*36 + lk4), A  + (size_t)(t0+m)*Cc + c0 + lk4);      \
            CP16(sptr(Bd + m*36 + lk4), Wt + (size_t)(j0+m)*Cc + c0 + lk4);      \
        }                                                                        \
    }

    LOAD_STAGE_O(0, 0); CP_COMMIT();

#pragma unroll 1
    for (int s = 0; s < 16; s++) {
        if (s < 15) { LOAD_STAGE_O(s+1, (s+1)&1); CP_COMMIT(); CP_WAIT(1); }
        else        { CP_WAIT(0); }
        __syncthreads();

        const float* Ac = As + (s&1)*4608;
        const float* Bc = Bs + (s&1)*4608;
#pragma unroll
        for (int kk = 0; kk < 4; kk++) {
            const int kb = kk*8;
            unsigned af[4][4], bf[4][2];
#pragma unroll
            for (int i = 0; i < 4; i++) {
                int m = wm*64 + 16*i + r;
                af[i][0] = f2tf(Ac[ m    *36 + kb + q]);
                af[i][1] = f2tf(Ac[(m+8) *36 + kb + q]);
                af[i][2] = f2tf(Ac[ m    *36 + kb + 4 + q]);
                af[i][3] = f2tf(Ac[(m+8) *36 + kb + 4 + q]);
            }
#pragma unroll
            for (int j = 0; j < 4; j++) {
                int n = wn*32 + 8*j + r;
                bf[j][0] = f2tf(Bc[n*36 + kb + q]);
                bf[j][1] = f2tf(Bc[n*36 + kb + 4 + q]);
            }
#pragma unroll
            for (int i = 0; i < 4; i++)
#pragma unroll
                for (int j = 0; j < 4; j++)
                    mma_tf32(acc[i][j], af[i], bf[j]);
        }
        __syncthreads();
    }
#undef LOAD_STAGE_O

    // ---- epilogue: bias + residual, write (B,C,N) ----
#pragma unroll
    for (int j = 0; j < 4; j++) {
        int jj0 = j0 + wn*32 + 8*j + 2*q;
#pragma unroll
        for (int col = 0; col < 2; col++) {
            int jj = jj0 + col;
            float bj = bias[jj];
            size_t rowbase = ((size_t)b*Cc + jj)*Nn;
#pragma unroll
            for (int i = 0; i < 4; i++) {
#pragma unroll
                for (int half = 0; half < 2; half++) {
                    int n = n0 + wm*64 + 16*i + r + 8*half;
                    size_t o = rowbase + n;
                    out[o] = acc[i][j][2*half + col] + bj + resid[o];
                }
            }
        }
    }
}

// ---------------- windowed attention: one block per (head, window) ----------
__global__ __launch_bounds__(256) void attn_kernel()
{
    __shared__ __align__(16) float Qs[4096];   // Q^T (d-major, swizzled); later aliased as P
    __shared__ __align__(16) float Ks[4096];   // K^T (d-major, swizzled)
    __shared__ __align__(16) float Vs[4096];   // V   (k-major)

    const int bx  = blockIdx.x;     // 0..4095
    const int h   = bx >> 9;
    const int win = bx & 511;
    const int b   = win >> 6;
    const int w   = win & 63;
    const int wy  = w >> 3, wx = w & 7;
    const int tid = threadIdx.x;

    const int tok0 = tid >> 4;              // 0..15
    const int d4   = (tid & 15) << 2;       // 0..60
    const size_t baseQK = ((size_t)b*NHh + h)*Nn*Dd;
    const int sw = ((d4 >> 2) & 15) << 2;
#pragma unroll
    for (int rr = 0; rr < 4; rr++) {
        int t = tok0 + 16*rr;
        int n = ((wy << 3) + (t >> 3))*64 + (wx << 3) + (t & 7);
        const float4 q4 = *(const float4*)(g_Q + baseQK + (size_t)n*Dd + d4);
        const float4 k4 = *(const float4*)(g_K + baseQK + (size_t)n*Dd + d4);
        const float4 v4 = *(const float4*)(g_V + baseQK + (size_t)n*Dd + d4);
        int ts = t ^ sw;
        Qs[(d4+0)*64 + ts] = q4.x;  Qs[(d4+1)*64 + ts] = q4.y;
        Qs[(d4+2)*64 + ts] = q4.z;  Qs[(d4+3)*64 + ts] = q4.w;
        Ks[(d4+0)*64 + ts] = k4.x;  Ks[(d4+1)*64 + ts] = k4.y;
        Ks[(d4+2)*64 + ts] = k4.z;  Ks[(d4+3)*64 + ts] = k4.w;
        *(float4*)&Vs[t*64 + d4] = v4;
    }
    __syncthreads();

    const int tx = tid & 15, ty = tid >> 4;
    float s[4][4];
#pragma unroll
    for (int i = 0; i < 4; i++)
#pragma unroll
        for (int j = 0; j < 4; j++) s[i][j] = 0.f;

#pragma unroll 4
    for (int d = 0; d < 64; d++) {
        int swd = ((d >> 2) & 15) << 2;
        float qr[4], kr[4];
#pragma unroll
        for (int i = 0; i < 4; i++) qr[i] = Qs[d*64 + ((ty + 16*i) ^ swd)];
#pragma unroll
        for (int j = 0; j < 4; j++) kr[j] = Ks[d*64 + ((tx + 16*j) ^ swd)];
#pragma unroll
        for (int i = 0; i < 4; i++)
#pragma unroll
            for (int j = 0; j < 4; j++) s[i][j] = fmaf(qr[i], kr[j], s[i][j]);
    }
    __syncthreads();   // everyone done reading Qs before it becomes P

    const float* bh = g_bias + (h << 12);
    float* Ps = Qs;
#pragma unroll
    for (int i = 0; i < 4; i++) {
        int qi = ty + 16*i;
        float m = -1e30f;
#pragma unroll
        for (int j = 0; j < 4; j++) {
            float v = fmaf(s[i][j], 0.125f, bh[qi*64 + tx + 16*j]);
            s[i][j] = v;
            m = fmaxf(m, v);
        }
#pragma unroll
        for (int off = 8; off; off >>= 1)
            m = fmaxf(m, __shfl_xor_sync(0xffffffffu, m, off));
        float sum = 0.f;
#pragma unroll
        for (int j = 0; j < 4; j++) {
            float e = expf(s[i][j] - m);
            s[i][j] = e;
            sum += e;
        }
#pragma unroll
        for (int off = 8; off; off >>= 1)
            sum += __shfl_xor_sync(0xffffffffu, sum, off);
        float inv = 1.f / sum;
#pragma unroll
        for (int j = 0; j < 4; j++)
            Ps[qi*64 + tx + 16*j] = s[i][j] * inv;
    }
    __syncthreads();

    float o[4][4];
#pragma unroll
    for (int i = 0; i < 4; i++)
#pragma unroll
        for (int j = 0; j < 4; j++) o[i][j] = 0.f;

#pragma unroll 4
    for (int k = 0; k < 64; k++) {
        float pr[4], vr[4];
#pragma unroll
        for (int i = 0; i < 4; i++) pr[i] = Ps[(ty + 16*i)*64 + k];
#pragma unroll
        for (int j = 0; j < 4; j++) vr[j] = Vs[k*64 + tx + 16*j];
#pragma unroll
        for (int i = 0; i < 4; i++)
#pragma unroll
            for (int j = 0; j < 4; j++) o[i][j] = fmaf(pr[i], vr[j], o[i][j]);
    }

#pragma unroll
    for (int i = 0; i < 4; i++) {
        int t = ty + 16*i;
        int n = ((wy << 3) + (t >> 3))*64 + (wx << 3) + (t & 7);
        size_t base = ((size_t)b*Nn + n)*Cc + (h << 6);
#pragma unroll
        for (int j = 0; j < 4; j++)
            g_AO[base + tx + 16*j] = o[i][j];
    }
}

// ---------------- host side ----------------
extern "C" void kernel_launch(void* const* d_in, const int* in_sizes, int n_in,
                              void* d_out, int out_size)
{
    const float* q    = (const float*)d_in[0];
    const float* kv   = (const float*)d_in[1];
    const float* gq   = (const float*)d_in[2];
    const float* bqln = (const float*)d_in[3];
    const float* gkv  = (const float*)d_in[4];
    const float* bkvln= (const float*)d_in[5];
    const float* Wq   = (const float*)d_in[6];
    const float* bq   = (const float*)d_in[7];
    const float* Wk   = (const float*)d_in[8];
    const float* bk   = (const float*)d_in[9];
    const float* Wv   = (const float*)d_in[10];
    const float* bv   = (const float*)d_in[11];
    const float* Wo   = (const float*)d_in[12];
    const float* bo   = (const float*)d_in[13];
    const float* tbl  = (const float*)d_in[14];
    float* out = (float*)d_out;

    void* p;
    cudaGetSymbolAddress(&p, g_qn);  float* qn  = (float*)p;
    cudaGetSymbolAddress(&p, g_kvn); float* kvn = (float*)p;
    cudaGetSymbolAddress(&p, g_Q);   float* Qb  = (float*)p;
    cudaGetSymbolAddress(&p, g_K);   float* Kb  = (float*)p;
    cudaGetSymbolAddress(&p, g_V);   float* Vb  = (float*)p;
    cudaGetSymbolAddress(&p, g_AO);  float* AO  = (float*)p;

    const int SMEM_QKV = (2*32*128 + 2*128*36) * 4;   // 69632 B
    const int SMEM_O   = (4*128*36) * 4;              // 73728 B
    cudaFuncSetAttribute(gemm_qkv_tc<true>,  cudaFuncAttributeMaxDynamicSharedMemorySize, SMEM_QKV);
    cudaFuncSetAttribute(gemm_qkv_tc<false>, cudaFuncAttributeMaxDynamicSharedMemorySize, SMEM_QKV);
    cudaFuncSetAttribute(gemm_o_tc,          cudaFuncAttributeMaxDynamicSharedMemorySize, SMEM_O);

    // layernorms (channel-major in and out)
    ln_kernel<<<256, 128>>>(q,  gq,  bqln,  qn);
    ln_kernel<<<256, 128>>>(kv, gkv, bkvln, kvn);

    // rope + bias tables
    rope_kernel<<<(Nn*32)/256, 256>>>();
    bias_kernel<<<(NHh*64*64)/256, 256>>>(tbl);

    // projections (rope fused for Q and K), tf32 tensor cores
    dim3 gg(256, 4);
    gemm_qkv_tc<true ><<<gg, 256, SMEM_QKV>>>(qn,  Wq, bq, Qb);
    gemm_qkv_tc<true ><<<gg, 256, SMEM_QKV>>>(kvn, Wk, bk, Kb);
    gemm_qkv_tc<false><<<gg, 256, SMEM_QKV>>>(kvn, Wv, bv, Vb);

    // windowed attention
    attn_kernel<<<NHh * Bb * 64, 256>>>();

    // output projection + bias + residual, straight into (B,C,H,W)
    gemm_o_tc<<<gg, 256, SMEM_O>>>(AO, Wo, bo, qn, out);
}

// round 4
// speedup vs baseline: 3.7744x; 1.4793x over previous
#include <cuda_runtime.h>
#include <cuda_bf16.h>
#include <math.h>

#define Bb   8
#define Cc   512
#define Nn   4096
#define NHh  8
#define Dd   64
#define EPSf 1e-5f

typedef __nv_bfloat16 bf16;

// ---------------- scratch (device globals; no allocation) ----------------
__device__ float g_qn  [Bb*Cc*Nn];        // layernormed q, (B,C,N) fp32 (residual)
__device__ bf16  g_qnh [Bb*Cc*Nn];        // bf16 copy for GEMM A
__device__ bf16  g_kvnh[Bb*Cc*Nn];
__device__ bf16  g_Wh  [4*Cc*Cc];         // Wq,Wk,Wv,Wo in bf16
__device__ bf16  g_Qh  [Bb*NHh*Nn*Dd];    // (B,NH,N,D) rope applied
__device__ bf16  g_Kh  [Bb*NHh*Nn*Dd];
__device__ bf16  g_Vh  [Bb*NHh*Nn*Dd];
__device__ bf16  g_AOh [Bb*Nn*Cc];        // attention out, (B,N,C)
__device__ float g_sin [Nn*32];
__device__ float g_cos [Nn*32];
__device__ float g_bias[NHh*64*64];       // (NH, Ws, Ws)

// ---------------- helpers ----------------
__device__ __forceinline__ unsigned sptr(const void* p) {
    return (unsigned)__cvta_generic_to_shared(p);
}
#define CP16(d, s)  asm volatile("cp.async.cg.shared.global [%0], [%1], 16;" :: "r"(d), "l"(s))
#define CP_COMMIT() asm volatile("cp.async.commit_group;")
#define CP_WAIT(n)  asm volatile("cp.async.wait_group %0;" :: "n"(n))

__device__ __forceinline__ void ldsm_x4(unsigned& r0, unsigned& r1, unsigned& r2, unsigned& r3, unsigned a) {
    asm volatile("ldmatrix.sync.aligned.m8n8.x4.shared.b16 {%0,%1,%2,%3}, [%4];"
                 : "=r"(r0), "=r"(r1), "=r"(r2), "=r"(r3) : "r"(a));
}
__device__ __forceinline__ void ldsm_x4t(unsigned& r0, unsigned& r1, unsigned& r2, unsigned& r3, unsigned a) {
    asm volatile("ldmatrix.sync.aligned.m8n8.x4.trans.shared.b16 {%0,%1,%2,%3}, [%4];"
                 : "=r"(r0), "=r"(r1), "=r"(r2), "=r"(r3) : "r"(a));
}
__device__ __forceinline__ void mma_bf16(float* c, const unsigned* a, const unsigned* b) {
    asm volatile(
        "mma.sync.aligned.m16n8k16.row.col.f32.bf16.bf16.f32 "
        "{%0,%1,%2,%3}, {%4,%5,%6,%7}, {%8,%9}, {%0,%1,%2,%3};"
        : "+f"(c[0]), "+f"(c[1]), "+f"(c[2]), "+f"(c[3])
        : "r"(a[0]), "r"(a[1]), "r"(a[2]), "r"(a[3]), "r"(b[0]), "r"(b[1]));
}
__device__ __forceinline__ unsigned packbf(float lo, float hi) {
    unsigned d; asm("cvt.rn.bf16x2.f32 %0, %1, %2;" : "=r"(d) : "f"(hi), "f"(lo)); return d;
}

// ---------------- weight convert fp32 -> bf16 (all 4 matrices) --------------
__global__ void wcvt_kernel(const float* __restrict__ w0, const float* __restrict__ w1,
                            const float* __restrict__ w2, const float* __restrict__ w3)
{
    int i = blockIdx.x * blockDim.x + threadIdx.x;     // 0 .. Cc*Cc-1
    g_Wh[0*Cc*Cc + i] = __float2bfloat16_rn(w0[i]);
    g_Wh[1*Cc*Cc + i] = __float2bfloat16_rn(w1[i]);
    g_Wh[2*Cc*Cc + i] = __float2bfloat16_rn(w2[i]);
    g_Wh[3*Cc*Cc + i] = __float2bfloat16_rn(w3[i]);
}

// ---------------- layernorm over C, channel-major in/out ----------------
template<bool F32OUT>
__global__ __launch_bounds__(128) void ln_kernel(const float* __restrict__ x,
                                                 const float* __restrict__ g,
                                                 const float* __restrict__ bt,
                                                 float* __restrict__ yf,
                                                 bf16* __restrict__ yh)
{
    int idx = blockIdx.x * blockDim.x + threadIdx.x;   // 0..B*N-1
    int b = idx >> 12;
    int n = idx & 4095;
    const float* xp = x + (size_t)b*Cc*Nn + n;
    float s = 0.f, s2 = 0.f;
#pragma unroll 16
    for (int c = 0; c < Cc; c++) {
        float v = xp[(size_t)c*Nn];
        s += v; s2 = fmaf(v, v, s2);
    }
    float mu  = s * (1.f/Cc);
    float var = s2 * (1.f/Cc) - mu*mu;
    float inv = rsqrtf(var + EPSf);
    float* yfp = yf + (size_t)b*Cc*Nn + n;
    bf16*  yhp = yh + (size_t)b*Cc*Nn + n;
#pragma unroll 16
    for (int c = 0; c < Cc; c++) {
        float v = xp[(size_t)c*Nn];
        float o = (v - mu) * inv * g[c] + bt[c];
        if (F32OUT) yfp[(size_t)c*Nn] = o;
        yhp[(size_t)c*Nn] = __float2bfloat16_rn(o);
    }
}

// ---------------- rope table (double precision) ----------------
__global__ void rope_kernel()
{
    int i = blockIdx.x * blockDim.x + threadIdx.x;     // Nn*32
    int n = i >> 5, k = i & 31;
    double invf = exp((-2.0 * (double)k / 64.0) * log(10000.0));
    double ang  = (double)n * invf;
    g_sin[i] = (float)sin(ang);
    g_cos[i] = (float)cos(ang);
}

// ---------------- relative position bias table ----------------
__global__ void bias_kernel(const float* __restrict__ table)
{
    int i = blockIdx.x * blockDim.x + threadIdx.x;     // NH*4096
    int h  = i >> 12;
    int qi = (i >> 6) & 63, ki = i & 63;
    int dh = (qi >> 3) - (ki >> 3) + 7;
    int dw = (qi & 7)  - (ki & 7)  + 7;
    g_bias[i] = table[(dh * 15 + dw) * NHh + h];
}

// ================= bf16 GEMM (TN): QKV projections ==================
// A bf16 channel-major (B,C,N); W bf16 (C_out, C_in). Out bf16 (B,NH,N,D),
// optional fused RoPE (fp32). Block 128m x 128n, BK=32, 8 warps (2m x 4n).
// As: [k=32][m=128] with 16B-chunk XOR swizzle (A frags via ldmatrix.trans).
// Bs: [n=128][k=40-padded] (B frags via ldmatrix).
template<bool ROPE>
__global__ __launch_bounds__(256) void gemm_qkv_bf(const bf16* __restrict__ A,
                                                   const bf16* __restrict__ W,
                                                   const float* __restrict__ bias,
                                                   bf16* __restrict__ out)
{
    __shared__ __align__(16) bf16 As[2][32*128];
    __shared__ __align__(16) bf16 Bs[2][128*40];

    const int t0 = blockIdx.x * 128;
    const int b  = t0 >> 12;
    const int n0 = t0 & 4095;
    const int j0 = blockIdx.y * 128;
    const int tid = threadIdx.x;
    const int lane = tid & 31, wid = tid >> 5;
    const int wm = wid & 1, wn = wid >> 1;
    const int r = lane >> 2, q = lane & 3;
    const int grp = lane >> 3, lr = lane & 7;

    const bf16* Ab = A + (size_t)b*Cc*Nn + n0;

    float acc[4][4][4];
#pragma unroll
    for (int i = 0; i < 4; i++)
#pragma unroll
        for (int j = 0; j < 4; j++)
#pragma unroll
            for (int k = 0; k < 4; k++) acc[i][j][k] = 0.f;

#define LOAD_QKV(S, BUF)                                                        \
    {                                                                           \
        int c0 = (S)*32;                                                        \
        _Pragma("unroll")                                                       \
        for (int u = 0; u < 2; u++) {                                           \
            int ac = tid*2 + u;                                                 \
            int k = ac >> 4, mc = ac & 15;                                      \
            CP16(sptr((char*)As[BUF] + k*256 + ((mc ^ (k&7)) << 4)),            \
                 Ab + (size_t)(c0+k)*Nn + mc*8);                                \
        }                                                                       \
        _Pragma("unroll")                                                       \
        for (int u = 0; u < 2; u++) {                                           \
            int bc = tid*2 + u;                                                 \
            int n = bc >> 2, kc = bc & 3;                                       \
            CP16(sptr(Bs[BUF] + n*40 + kc*8),                                   \
                 W + (size_t)(j0+n)*Cc + c0 + kc*8);                            \
        }                                                                       \
    }

    LOAD_QKV(0, 0); CP_COMMIT();

#pragma unroll 1
    for (int s = 0; s < 16; s++) {
        if (s < 15) { LOAD_QKV(s+1, (s+1)&1); CP_COMMIT(); CP_WAIT(1); }
        else        { CP_WAIT(0); }
        __syncthreads();

        const bf16* Ac = As[s&1];
        const bf16* Bc = Bs[s&1];
#pragma unroll
        for (int kk = 0; kk < 2; kk++) {
            unsigned af[4][4], bfr[4][2];
#pragma unroll
            for (int i = 0; i < 4; i++) {
                int k  = kk*16 + ((grp & 2) ? 8 : 0) + lr;
                int mc = wm*8 + 2*i + (grp & 1);
                ldsm_x4t(af[i][0], af[i][1], af[i][2], af[i][3],
                         sptr((const char*)Ac + k*256 + ((mc ^ (k&7)) << 4)));
            }
#pragma unroll
            for (int jg = 0; jg < 2; jg++) {
                int n = wn*32 + jg*16 + ((grp & 2) ? 8 : 0) + lr;
                int ka = (grp & 1) ? 8 : 0;
                ldsm_x4(bfr[jg*2][0], bfr[jg*2][1], bfr[jg*2+1][0], bfr[jg*2+1][1],
                        sptr(Bc + n*40 + kk*16 + ka));
            }
#pragma unroll
            for (int i = 0; i < 4; i++)
#pragma unroll
                for (int j = 0; j < 4; j++)
                    mma_bf16(acc[i][j], af[i], bfr[j]);
        }
        __syncthreads();
    }
#undef LOAD_QKV

    // ---- epilogue: bias (+ RoPE, fp32), store bf16 ----
#pragma unroll
    for (int i = 0; i < 4; i++) {
        int ntok = n0 + wm*64 + 16*i + r;
#pragma unroll
        for (int j = 0; j < 4; j++) {
            int jj = j0 + wn*32 + 8*j + 2*q;
            int hh = jj >> 6;
            int d  = jj & 63;                  // even
            float bv0 = bias[jj], bv1 = bias[jj+1];
#pragma unroll
            for (int half = 0; half < 2; half++) {
                int n = ntok + 8*half;
                float v0 = acc[i][j][2*half+0] + bv0;
                float v1 = acc[i][j][2*half+1] + bv1;
                float x, y;
                if (ROPE) {
                    int p = (n << 5) + (d >> 1);
                    float sv = g_sin[p], cv = g_cos[p];
                    x = v0*cv - v1*sv;
                    y = v0*sv + v1*cv;
                } else { x = v0; y = v1; }
                *(__nv_bfloat162*)&out[(((size_t)b*NHh + hh)*Nn + n)*Dd + d] =
                    __floats2bfloat162_rn(x, y);
            }
        }
    }
}

// ================= bf16 GEMM (NT): output projection ==================
// A = g_AOh (B,N,C) bf16 row-major [m][k]; W = Wo bf16 [n][k];
// out fp32 (B,C,N) = A@Wo^T + bo + resid(fp32).
__global__ __launch_bounds__(256) void gemm_o_bf(const bf16* __restrict__ A,
                                                 const bf16* __restrict__ W,
                                                 const float* __restrict__ bias,
                                                 const float* __restrict__ resid,
                                                 float* __restrict__ out)
{
    __shared__ __align__(16) bf16 As[2][128*40];
    __shared__ __align__(16) bf16 Bs[2][128*40];

    const int t0 = blockIdx.x * 128;
    const int b  = t0 >> 12;
    const int n0 = t0 & 4095;
    const int j0 = blockIdx.y * 128;
    const int tid = threadIdx.x;
    const int lane = tid & 31, wid = tid >> 5;
    const int wm = wid & 1, wn = wid >> 1;
    const int r = lane >> 2, q = lane & 3;
    const int grp = lane >> 3, lr = lane & 7;

    float acc[4][4][4];
#pragma unroll
    for (int i = 0; i < 4; i++)
#pragma unroll
        for (int j = 0; j < 4; j++)
#pragma unroll
            for (int k = 0; k < 4; k++) acc[i][j][k] = 0.f;

#define LOAD_O(S, BUF)                                                          \
    {                                                                           \
        int c0 = (S)*32;                                                        \
        _Pragma("unroll")                                                       \
        for (int u = 0; u < 2; u++) {                                           \
            int ac = tid*2 + u;                                                 \
            int m = ac >> 2, kc = ac & 3;                                       \
            CP16(sptr(As[BUF] + m*40 + kc*8),                                   \
                 A + (size_t)(t0+m)*Cc + c0 + kc*8);                            \
        }                                                                       \
        _Pragma("unroll")                                                       \
        for (int u = 0; u < 2; u++) {                                           \
            int bc = tid*2 + u;                                                 \
            int n = bc >> 2, kc = bc & 3;                                       \
            CP16(sptr(Bs[BUF] + n*40 + kc*8),                                   \
                 W + (size_t)(j0+n)*Cc + c0 + kc*8);                            \
        }                                                                       \
    }

    LOAD_O(0, 0); CP_COMMIT();

#pragma unroll 1
    for (int s = 0; s < 16; s++) {
        if (s < 15) { LOAD_O(s+1, (s+1)&1); CP_COMMIT(); CP_WAIT(1); }
        else        { CP_WAIT(0); }
        __syncthreads();

        const bf16* Ac = As[s&1];
        const bf16* Bc = Bs[s&1];
#pragma unroll
        for (int kk = 0; kk < 2; kk++) {
            unsigned af[4][4], bfr[4][2];
#pragma unroll
            for (int i = 0; i < 4; i++) {
                int m  = wm*64 + 16*i + ((grp & 1) ? 8 : 0) + lr;
                int ka = (grp & 2) ? 8 : 0;
                ldsm_x4(af[i][0], af[i][1], af[i][2], af[i][3],
                        sptr(Ac + m*40 + kk*16 + ka));
            }
#pragma unroll
            for (int jg = 0; jg < 2; jg++) {
                int n = wn*32 + jg*16 + ((grp & 2) ? 8 : 0) + lr;
                int ka = (grp & 1) ? 8 : 0;
                ldsm_x4(bfr[jg*2][0], bfr[jg*2][1], bfr[jg*2+1][0], bfr[jg*2+1][1],
                        sptr(Bc + n*40 + kk*16 + ka));
            }
#pragma unroll
            for (int i = 0; i < 4; i++)
#pragma unroll
                for (int j = 0; j < 4; j++)
                    mma_bf16(acc[i][j], af[i], bfr[j]);
        }
        __syncthreads();
    }
#undef LOAD_O

    // ---- epilogue: bias + residual (fp32), write (B,C,N) ----
#pragma unroll
    for (int j = 0; j < 4; j++) {
        int jj0 = j0 + wn*32 + 8*j + 2*q;
#pragma unroll
        for (int col = 0; col < 2; col++) {
            int jj = jj0 + col;
            float bj = bias[jj];
            size_t rowbase = ((size_t)b*Cc + jj)*Nn;
#pragma unroll
            for (int i = 0; i < 4; i++) {
#pragma unroll
                for (int half = 0; half < 2; half++) {
                    int n = n0 + wm*64 + 16*i + r + 8*half;
                    size_t o = rowbase + n;
                    out[o] = acc[i][j][2*half + col] + bj + resid[o];
                }
            }
        }
    }
}

// ---------------- windowed attention (bf16 mma), 1 block per (head, window) --
__global__ __launch_bounds__(128) void attn_bf()
{
    __shared__ __align__(16) bf16 Qs[64*72];
    __shared__ __align__(16) bf16 Ks[64*72];
    __shared__ __align__(16) bf16 Vs[64*72];

    const int bx  = blockIdx.x;     // 0..4095
    const int h   = bx >> 9;
    const int win = bx & 511;
    const int b   = win >> 6;
    const int w   = win & 63;
    const int wy  = w >> 3, wx = w & 7;
    const int tid = threadIdx.x;
    const int lane = tid & 31, wid = tid >> 5;
    const int grp = lane >> 3, lr = lane & 7;

    // ---- load Q/K/V tiles (64 tokens x 64 d, bf16) ----
    {
        int t  = tid & 63;
        int c2 = tid >> 6;                       // 0/1: which 32-half chunk
        int n_t = ((wy*8 + (t >> 3)) << 6) + wx*8 + (t & 7);
        size_t base = (((size_t)b*NHh + h)*Nn + n_t)*Dd;
#pragma unroll
        for (int u = 0; u < 4; u++) {
            int off = c2*32 + u*8;               // halves
            uint4 qv = *(const uint4*)((const char*)g_Qh + (base + off)*2);
            uint4 kv = *(const uint4*)((const char*)g_Kh + (base + off)*2);
            uint4 vv = *(const uint4*)((const char*)g_Vh + (base + off)*2);
            *(uint4*)((char*)Qs + (t*72 + off)*2) = qv;
            *(uint4*)((char*)Ks + (t*72 + off)*2) = kv;
            *(uint4*)((char*)Vs + (t*72 + off)*2) = vv;
        }
    }
    __syncthreads();

    const int m0 = wid * 16;

    // ---- Q fragments (A operand) ----
    unsigned af[4][4];
#pragma unroll
    for (int kk = 0; kk < 4; kk++) {
        int m  = m0 + ((grp & 1) ? 8 : 0) + lr;
        int ka = (grp & 2) ? 8 : 0;
        ldsm_x4(af[kk][0], af[kk][1], af[kk][2], af[kk][3],
                sptr(Qs + m*72 + kk*16 + ka));
    }

    // ---- S = Q K^T ----
    float s[8][4];
#pragma unroll
    for (int j = 0; j < 8; j++)
#pragma unroll
        for (int c = 0; c < 4; c++) s[j][c] = 0.f;

#pragma unroll
    for (int kk = 0; kk < 4; kk++) {
        unsigned bfr[8][2];
#pragma unroll
        for (int jg = 0; jg < 4; jg++) {
            int n  = jg*16 + ((grp & 2) ? 8 : 0) + lr;
            int ka = (grp & 1) ? 8 : 0;
            ldsm_x4(bfr[jg*2][0], bfr[jg*2][1], bfr[jg*2+1][0], bfr[jg*2+1][1],
                    sptr(Ks + n*72 + kk*16 + ka));
        }
#pragma unroll
        for (int j = 0; j < 8; j++)
            mma_bf16(s[j], af[kk], bfr[j]);
    }

    // ---- scale + bias + softmax (fp32, quad shuffles) ----
    const float* bh = g_bias + (h << 12);
    const int row0 = m0 + (lane >> 2);
    const int col0 = 2 * (lane & 3);
    float mx0 = -1e30f, mx1 = -1e30f;
#pragma unroll
    for (int j = 0; j < 8; j++) {
        float2 b0 = *(const float2*)(bh + row0*64 + 8*j + col0);
        float2 b1 = *(const float2*)(bh + (row0+8)*64 + 8*j + col0);
        s[j][0] = fmaf(s[j][0], 0.125f, b0.x);
        s[j][1] = fmaf(s[j][1], 0.125f, b0.y);
        s[j][2] = fmaf(s[j][2], 0.125f, b1.x);
        s[j][3] = fmaf(s[j][3], 0.125f, b1.y);
        mx0 = fmaxf(mx0, fmaxf(s[j][0], s[j][1]));
        mx1 = fmaxf(mx1, fmaxf(s[j][2], s[j][3]));
    }
    mx0 = fmaxf(mx0, __shfl_xor_sync(0xffffffffu, mx0, 1));
    mx0 = fmaxf(mx0, __shfl_xor_sync(0xffffffffu, mx0, 2));
    mx1 = fmaxf(mx1, __shfl_xor_sync(0xffffffffu, mx1, 1));
    mx1 = fmaxf(mx1, __shfl_xor_sync(0xffffffffu, mx1, 2));

    float sum0 = 0.f, sum1 = 0.f;
#pragma unroll
    for (int j = 0; j < 8; j++) {
        s[j][0] = __expf(s[j][0] - mx0);
        s[j][1] = __expf(s[j][1] - mx0);
        s[j][2] = __expf(s[j][2] - mx1);
        s[j][3] = __expf(s[j][3] - mx1);
        sum0 += s[j][0] + s[j][1];
        sum1 += s[j][2] + s[j][3];
    }
    sum0 += __shfl_xor_sync(0xffffffffu, sum0, 1);
    sum0 += __shfl_xor_sync(0xffffffffu, sum0, 2);
    sum1 += __shfl_xor_sync(0xffffffffu, sum1, 1);
    sum1 += __shfl_xor_sync(0xffffffffu, sum1, 2);
    float inv0 = 1.f / sum0, inv1 = 1.f / sum1;

    // ---- O = P V (P from S-frags packed as A-frags; V via ldmatrix.trans) ----
    float o[8][4];
#pragma unroll
    for (int j = 0; j < 8; j++)
#pragma unroll
        for (int c = 0; c < 4; c++) o[j][c] = 0.f;

#pragma unroll
    for (int kk = 0; kk < 4; kk++) {
        unsigned pa[4];
        pa[0] = packbf(s[2*kk  ][0], s[2*kk  ][1]);
        pa[1] = packbf(s[2*kk  ][2], s[2*kk  ][3]);
        pa[2] = packbf(s[2*kk+1][0], s[2*kk+1][1]);
        pa[3] = packbf(s[2*kk+1][2], s[2*kk+1][3]);
        unsigned vb[8][2];
#pragma unroll
        for (int jg = 0; jg < 4; jg++) {
            int rowk = kk*16 + ((grp & 1) ? 8 : 0) + lr;
            int cold = jg*16 + ((grp & 2) ? 8 : 0);
            ldsm_x4t(vb[jg*2][0], vb[jg*2][1], vb[jg*2+1][0], vb[jg*2+1][1],
                     sptr(Vs + rowk*72 + cold));
        }
#pragma unroll
        for (int j = 0; j < 8; j++)
            mma_bf16(o[j], pa, vb[j]);
    }

    // ---- store to g_AOh (B,N,C) bf16 ----
    {
        int tA = row0, tB = row0 + 8;
        int nA = ((wy*8 + (tA >> 3)) << 6) + wx*8 + (tA & 7);
        int nB = ((wy*8 + (tB >> 3)) << 6) + wx*8 + (tB & 7);
        size_t baseA = ((size_t)b*Nn + nA)*Cc + (h << 6);
        size_t baseB = ((size_t)b*Nn + nB)*Cc + (h << 6);
#pragma unroll
        for (int j = 0; j < 8; j++) {
            int d = 8*j + col0;
            *(__nv_bfloat162*)&g_AOh[baseA + d] =
                __floats2bfloat162_rn(o[j][0]*inv0, o[j][1]*inv0);
            *(__nv_bfloat162*)&g_AOh[baseB + d] =
                __floats2bfloat162_rn(o[j][2]*inv1, o[j][3]*inv1);
        }
    }
}

// ---------------- host side ----------------
extern "C" void kernel_launch(void* const* d_in, const int* in_sizes, int n_in,
                              void* d_out, int out_size)
{
    const float* q    = (const float*)d_in[0];
    const float* kv   = (const float*)d_in[1];
    const float* gq   = (const float*)d_in[2];
    const float* bqln = (const float*)d_in[3];
    const float* gkv  = (const float*)d_in[4];
    const float* bkvln= (const float*)d_in[5];
    const float* Wq   = (const float*)d_in[6];
    const float* bq   = (const float*)d_in[7];
    const float* Wk   = (const float*)d_in[8];
    const float* bk   = (const float*)d_in[9];
    const float* Wv   = (const float*)d_in[10];
    const float* bv   = (const float*)d_in[11];
    const float* Wo   = (const float*)d_in[12];
    const float* bo   = (const float*)d_in[13];
    const float* tbl  = (const float*)d_in[14];
    float* out = (float*)d_out;

    void* p;
    cudaGetSymbolAddress(&p, g_qn);   float* qn  = (float*)p;
    cudaGetSymbolAddress(&p, g_qnh);  bf16* qnh  = (bf16*)p;
    cudaGetSymbolAddress(&p, g_kvnh); bf16* kvnh = (bf16*)p;
    cudaGetSymbolAddress(&p, g_Wh);   bf16* Wh   = (bf16*)p;
    cudaGetSymbolAddress(&p, g_Qh);   bf16* Qb   = (bf16*)p;
    cudaGetSymbolAddress(&p, g_Kh);   bf16* Kb   = (bf16*)p;
    cudaGetSymbolAddress(&p, g_Vh);   bf16* Vb   = (bf16*)p;
    cudaGetSymbolAddress(&p, g_AOh);  bf16* AO   = (bf16*)p;

    // weight conversion (bf16), one launch for all 4 matrices
    wcvt_kernel<<<Cc*Cc/1024, 1024>>>(Wq, Wk, Wv, Wo);

    // layernorms
    ln_kernel<true ><<<256, 128>>>(q,  gq,  bqln,  qn, qnh);
    ln_kernel<false><<<256, 128>>>(kv, gkv, bkvln, qn, kvnh);

    // rope + bias tables
    rope_kernel<<<(Nn*32)/256, 256>>>();
    bias_kernel<<<(NHh*64*64)/256, 256>>>(tbl);

    // projections (rope fused for Q and K)
    dim3 gg(256, 4);
    gemm_qkv_bf<true ><<<gg, 256>>>(qnh,  Wh + 0*Cc*Cc, bq, Qb);
    gemm_qkv_bf<true ><<<gg, 256>>>(kvnh, Wh + 1*Cc*Cc, bk, Kb);
    gemm_qkv_bf<false><<<gg, 256>>>(kvnh, Wh + 2*Cc*Cc, bv, Vb);

    // windowed attention
    attn_bf<<<NHh * Bb * 64, 128>>>();

    // output projection + bias + residual -> (B,C,H,W)
    gemm_o_bf<<<gg, 256>>>(AO, Wh + 3*Cc*Cc, bo, qn, out);
}

// round 5
// speedup vs baseline: 4.2918x; 1.1371x over previous
#include <cuda_runtime.h>
#include <cuda_bf16.h>
#include <math.h>

#define Bb   8
#define Cc   512
#define Nn   4096
#define NHh  8
#define Dd   64
#define EPSf 1e-5f

typedef __nv_bfloat16 bf16;

// ---------------- scratch (device globals; no allocation) ----------------
__device__ float g_qn  [Bb*Cc*Nn];        // layernormed q, (B,C,N) fp32 (residual)
__device__ bf16  g_qnh [Bb*Cc*Nn];        // bf16 copy for GEMM A
__device__ bf16  g_kvnh[Bb*Cc*Nn];
__device__ bf16  g_Wh  [4*Cc*Cc];         // Wq,Wk,Wv,Wo in bf16
__device__ bf16  g_Qh  [Bb*NHh*Nn*Dd];    // (B,NH,N,D) rope applied
__device__ bf16  g_Kh  [Bb*NHh*Nn*Dd];
__device__ bf16  g_Vh  [Bb*NHh*Nn*Dd];
__device__ bf16  g_AOh [Bb*Nn*Cc];        // attention out, (B,N,C)
__device__ float g_sin [Nn*32];
__device__ float g_cos [Nn*32];
__device__ float g_bias[NHh*64*64];       // (NH, Ws, Ws)

// ---------------- helpers ----------------
__device__ __forceinline__ unsigned sptr(const void* p) {
    return (unsigned)__cvta_generic_to_shared(p);
}
#define CP16(d, s)  asm volatile("cp.async.cg.shared.global [%0], [%1], 16;" :: "r"(d), "l"(s))
#define CP_COMMIT() asm volatile("cp.async.commit_group;")
#define CP_WAIT(n)  asm volatile("cp.async.wait_group %0;" :: "n"(n))

__device__ __forceinline__ void ldsm_x4(unsigned& r0, unsigned& r1, unsigned& r2, unsigned& r3, unsigned a) {
    asm volatile("ldmatrix.sync.aligned.m8n8.x4.shared.b16 {%0,%1,%2,%3}, [%4];"
                 : "=r"(r0), "=r"(r1), "=r"(r2), "=r"(r3) : "r"(a));
}
__device__ __forceinline__ void ldsm_x4t(unsigned& r0, unsigned& r1, unsigned& r2, unsigned& r3, unsigned a) {
    asm volatile("ldmatrix.sync.aligned.m8n8.x4.trans.shared.b16 {%0,%1,%2,%3}, [%4];"
                 : "=r"(r0), "=r"(r1), "=r"(r2), "=r"(r3) : "r"(a));
}
__device__ __forceinline__ void mma_bf16(float* c, const unsigned* a, const unsigned* b) {
    asm volatile(
        "mma.sync.aligned.m16n8k16.row.col.f32.bf16.bf16.f32 "
        "{%0,%1,%2,%3}, {%4,%5,%6,%7}, {%8,%9}, {%0,%1,%2,%3};"
        : "+f"(c[0]), "+f"(c[1]), "+f"(c[2]), "+f"(c[3])
        : "r"(a[0]), "r"(a[1]), "r"(a[2]), "r"(a[3]), "r"(b[0]), "r"(b[1]));
}
__device__ __forceinline__ unsigned packbf(float lo, float hi) {
    unsigned d; asm("cvt.rn.bf16x2.f32 %0, %1, %2;" : "=r"(d) : "f"(hi), "f"(lo)); return d;
}

// ---------------- weight convert fp32 -> bf16 (all 4 matrices) --------------
__global__ void wcvt_kernel(const float* __restrict__ w0, const float* __restrict__ w1,
                            const float* __restrict__ w2, const float* __restrict__ w3)
{
    int i = blockIdx.x * blockDim.x + threadIdx.x;     // 0 .. Cc*Cc-1
    g_Wh[0*Cc*Cc + i] = __float2bfloat16_rn(w0[i]);
    g_Wh[1*Cc*Cc + i] = __float2bfloat16_rn(w1[i]);
    g_Wh[2*Cc*Cc + i] = __float2bfloat16_rn(w2[i]);
    g_Wh[3*Cc*Cc + i] = __float2bfloat16_rn(w3[i]);
}

// ---------------- layernorm over C, channel-major in/out ----------------
template<bool F32OUT>
__global__ __launch_bounds__(128) void ln_kernel(const float* __restrict__ x,
                                                 const float* __restrict__ g,
                                                 const float* __restrict__ bt,
                                                 float* __restrict__ yf,
                                                 bf16* __restrict__ yh)
{
    int idx = blockIdx.x * blockDim.x + threadIdx.x;   // 0..B*N-1
    int b = idx >> 12;
    int n = idx & 4095;
    const float* xp = x + (size_t)b*Cc*Nn + n;
    float s = 0.f, s2 = 0.f;
#pragma unroll 16
    for (int c = 0; c < Cc; c++) {
        float v = xp[(size_t)c*Nn];
        s += v; s2 = fmaf(v, v, s2);
    }
    float mu  = s * (1.f/Cc);
    float var = s2 * (1.f/Cc) - mu*mu;
    float inv = rsqrtf(var + EPSf);
    float* yfp = yf + (size_t)b*Cc*Nn + n;
    bf16*  yhp = yh + (size_t)b*Cc*Nn + n;
#pragma unroll 16
    for (int c = 0; c < Cc; c++) {
        float v = xp[(size_t)c*Nn];
        float o = (v - mu) * inv * g[c] + bt[c];
        if (F32OUT) yfp[(size_t)c*Nn] = o;
        yhp[(size_t)c*Nn] = __float2bfloat16_rn(o);
    }
}

// ---------------- rope table (fp32; downstream is bf16 anyway) --------------
__global__ void rope_kernel()
{
    int i = blockIdx.x * blockDim.x + threadIdx.x;     // Nn*32
    int n = i >> 5, k = i & 31;
    // inv_freq = 10000^(-k/32) = exp2(-k/32 * log2(10000))
    float invf = exp2f(-(float)k * (13.287712379549449f / 32.0f));
    float ang  = (float)n * invf;
    float sv, cv;
    sincosf(ang, &sv, &cv);
    g_sin[i] = sv;
    g_cos[i] = cv;
}

// ---------------- relative position bias table ----------------
__global__ void bias_kernel(const float* __restrict__ table)
{
    int i = blockIdx.x * blockDim.x + threadIdx.x;     // NH*4096
    int h  = i >> 12;
    int qi = (i >> 6) & 63, ki = i & 63;
    int dh = (qi >> 3) - (ki >> 3) + 7;
    int dw = (qi & 7)  - (ki & 7)  + 7;
    g_bias[i] = table[(dh * 15 + dw) * NHh + h];
}

// ================= bf16 GEMM (TN): merged Q/K/V projections ==================
// blockIdx.y in 0..11: seg = y>>2 selects {Q,K,V}; (y&3)*128 = output-col tile.
// A bf16 channel-major (B,C,N); W bf16 (C_out, C_in). Out bf16 (B,NH,N,D),
// fused RoPE for Q/K. Block 128m x 128n, BK=32, 3-stage cp.async pipeline.
// As: [k=32][m=128] with 16B-chunk XOR swizzle (A frags via ldmatrix.trans).
// Bs: [n=128][k=40-padded] (B frags via ldmatrix).
__global__ __launch_bounds__(256, 2) void gemm_qkv_bf(const bf16* __restrict__ Aq,
                                                      const bf16* __restrict__ Akv,
                                                      const float* __restrict__ bq,
                                                      const float* __restrict__ bk,
                                                      const float* __restrict__ bv,
                                                      bf16* __restrict__ outQ,
                                                      bf16* __restrict__ outK,
                                                      bf16* __restrict__ outV)
{
    extern __shared__ __align__(16) bf16 smraw[];
    bf16* As = smraw;                 // 3 x 32*128
    bf16* Bs = smraw + 3*32*128;      // 3 x 128*40

    const int seg = blockIdx.y >> 2;            // 0=Q 1=K 2=V
    const bf16*  A    = seg ? Akv : Aq;
    const bf16*  W    = g_Wh + (size_t)seg*Cc*Cc;
    const float* bias = (seg == 0) ? bq : (seg == 1) ? bk : bv;
    bf16*        out  = (seg == 0) ? outQ : (seg == 1) ? outK : outV;
    const bool   rope = (seg < 2);
    const int j0 = (blockIdx.y & 3) * 128;

    const int t0 = blockIdx.x * 128;
    const int b  = t0 >> 12;
    const int n0 = t0 & 4095;
    const int tid = threadIdx.x;
    const int lane = tid & 31, wid = tid >> 5;
    const int wm = wid & 1, wn = wid >> 1;
    const int r = lane >> 2, q = lane & 3;
    const int grp = lane >> 3, lr = lane & 7;

    const bf16* Ab = A + (size_t)b*Cc*Nn + n0;

    float acc[4][4][4];
#pragma unroll
    for (int i = 0; i < 4; i++)
#pragma unroll
        for (int j = 0; j < 4; j++)
#pragma unroll
            for (int k = 0; k < 4; k++) acc[i][j][k] = 0.f;

#define LOAD_QKV(S, BUF)                                                        \
    {                                                                           \
        bf16* Ad = As + (BUF)*4096;                                             \
        bf16* Bd = Bs + (BUF)*5120;                                             \
        int c0 = (S)*32;                                                        \
        _Pragma("unroll")                                                       \
        for (int u = 0; u < 2; u++) {                                           \
            int ac = tid*2 + u;                                                 \
            int k = ac >> 4, mc = ac & 15;                                      \
            CP16(sptr((char*)Ad + k*256 + ((mc ^ (k&7)) << 4)),                 \
                 Ab + (size_t)(c0+k)*Nn + mc*8);                                \
        }                                                                       \
        _Pragma("unroll")                                                       \
        for (int u = 0; u < 2; u++) {                                           \
            int bc = tid*2 + u;                                                 \
            int n = bc >> 2, kc = bc & 3;                                       \
            CP16(sptr(Bd + n*40 + kc*8),                                        \
                 W + (size_t)(j0+n)*Cc + c0 + kc*8);                            \
        }                                                                       \
    }

    LOAD_QKV(0, 0); CP_COMMIT();
    LOAD_QKV(1, 1); CP_COMMIT();

#pragma unroll 1
    for (int s = 0; s < 16; s++) {
        if (s < 15) { CP_WAIT(1); } else { CP_WAIT(0); }
        __syncthreads();
        if (s < 14) { LOAD_QKV(s+2, (s+2)%3); CP_COMMIT(); }

        const bf16* Ac = As + (s%3)*4096;
        const bf16* Bc = Bs + (s%3)*5120;
#pragma unroll
        for (int kk = 0; kk < 2; kk++) {
            unsigned af[4][4], bfr[4][2];
#pragma unroll
            for (int i = 0; i < 4; i++) {
                int k  = kk*16 + ((grp & 2) ? 8 : 0) + lr;
                int mc = wm*8 + 2*i + (grp & 1);
                ldsm_x4t(af[i][0], af[i][1], af[i][2], af[i][3],
                         sptr((const char*)Ac + k*256 + ((mc ^ (k&7)) << 4)));
            }
#pragma unroll
            for (int jg = 0; jg < 2; jg++) {
                int n = wn*32 + jg*16 + ((grp & 2) ? 8 : 0) + lr;
                int ka = (grp & 1) ? 8 : 0;
                ldsm_x4(bfr[jg*2][0], bfr[jg*2][1], bfr[jg*2+1][0], bfr[jg*2+1][1],
                        sptr(Bc + n*40 + kk*16 + ka));
            }
#pragma unroll
            for (int i = 0; i < 4; i++)
#pragma unroll
                for (int j = 0; j < 4; j++)
                    mma_bf16(acc[i][j], af[i], bfr[j]);
        }
    }
#undef LOAD_QKV

    // ---- epilogue: bias (+ RoPE, fp32), store bf16 ----
#pragma unroll
    for (int i = 0; i < 4; i++) {
        int ntok = n0 + wm*64 + 16*i + r;
#pragma unroll
        for (int j = 0; j < 4; j++) {
            int jj = j0 + wn*32 + 8*j + 2*q;
            int hh = jj >> 6;
            int d  = jj & 63;                  // even
            float bv0 = bias[jj], bv1 = bias[jj+1];
#pragma unroll
            for (int half = 0; half < 2; half++) {
                int n = ntok + 8*half;
                float v0 = acc[i][j][2*half+0] + bv0;
                float v1 = acc[i][j][2*half+1] + bv1;
                float x, y;
                if (rope) {
                    int p = (n << 5) + (d >> 1);
                    float sv = g_sin[p], cv = g_cos[p];
                    x = v0*cv - v1*sv;
                    y = v0*sv + v1*cv;
                } else { x = v0; y = v1; }
                *(__nv_bfloat162*)&out[(((size_t)b*NHh + hh)*Nn + n)*Dd + d] =
                    __floats2bfloat162_rn(x, y);
            }
        }
    }
}

// ================= bf16 GEMM (NT): output projection ==================
// A = g_AOh (B,N,C) bf16 row-major [m][k]; W = Wo bf16 [n][k];
// out fp32 (B,C,N) = A@Wo^T + bo + resid(fp32). 3-stage pipeline.
__global__ __launch_bounds__(256, 2) void gemm_o_bf(const bf16* __restrict__ A,
                                                    const bf16* __restrict__ W,
                                                    const float* __restrict__ bias,
                                                    const float* __restrict__ resid,
                                                    float* __restrict__ out)
{
    extern __shared__ __align__(16) bf16 smraw[];
    bf16* As = smraw;                 // 3 x 128*40
    bf16* Bs = smraw + 3*128*40;      // 3 x 128*40

    const int t0 = blockIdx.x * 128;
    const int b  = t0 >> 12;
    const int n0 = t0 & 4095;
    const int j0 = blockIdx.y * 128;
    const int tid = threadIdx.x;
    const int lane = tid & 31, wid = tid >> 5;
    const int wm = wid & 1, wn = wid >> 1;
    const int r = lane >> 2, q = lane & 3;
    const int grp = lane >> 3, lr = lane & 7;

    float acc[4][4][4];
#pragma unroll
    for (int i = 0; i < 4; i++)
#pragma unroll
        for (int j = 0; j < 4; j++)
#pragma unroll
            for (int k = 0; k < 4; k++) acc[i][j][k] = 0.f;

#define LOAD_O(S, BUF)                                                          \
    {                                                                           \
        bf16* Ad = As + (BUF)*5120;                                             \
        bf16* Bd = Bs + (BUF)*5120;                                             \
        int c0 = (S)*32;                                                        \
        _Pragma("unroll")                                                       \
        for (int u = 0; u < 2; u++) {                                           \
            int ac = tid*2 + u;                                                 \
            int m = ac >> 2, kc = ac & 3;                                       \
            CP16(sptr(Ad + m*40 + kc*8),                                        \
                 A + (size_t)(t0+m)*Cc + c0 + kc*8);                            \
        }                                                                       \
        _Pragma("unroll")                                                       \
        for (int u = 0; u < 2; u++) {                                           \
            int bc = tid*2 + u;                                                 \
            int n = bc >> 2, kc = bc & 3;                                       \
            CP16(sptr(Bd + n*40 + kc*8),                                        \
                 W + (size_t)(j0+n)*Cc + c0 + kc*8);                            \
        }                                                                       \
    }

    LOAD_O(0, 0); CP_COMMIT();
    LOAD_O(1, 1); CP_COMMIT();

#pragma unroll 1
    for (int s = 0; s < 16; s++) {
        if (s < 15) { CP_WAIT(1); } else { CP_WAIT(0); }
        __syncthreads();
        if (s < 14) { LOAD_O(s+2, (s+2)%3); CP_COMMIT(); }

        const bf16* Ac = As + (s%3)*5120;
        const bf16* Bc = Bs + (s%3)*5120;
#pragma unroll
        for (int kk = 0; kk < 2; kk++) {
            unsigned af[4][4], bfr[4][2];
#pragma unroll
            for (int i = 0; i < 4; i++) {
                int m  = wm*64 + 16*i + ((grp & 1) ? 8 : 0) + lr;
                int ka = (grp & 2) ? 8 : 0;
                ldsm_x4(af[i][0], af[i][1], af[i][2], af[i][3],
                        sptr(Ac + m*40 + kk*16 + ka));
            }
#pragma unroll
            for (int jg = 0; jg < 2; jg++) {
                int n = wn*32 + jg*16 + ((grp & 2) ? 8 : 0) + lr;
                int ka = (grp & 1) ? 8 : 0;
                ldsm_x4(bfr[jg*2][0], bfr[jg*2][1], bfr[jg*2+1][0], bfr[jg*2+1][1],
                        sptr(Bc + n*40 + kk*16 + ka));
            }
#pragma unroll
            for (int i = 0; i < 4; i++)
#pragma unroll
                for (int j = 0; j < 4; j++)
                    mma_bf16(acc[i][j], af[i], bfr[j]);
        }
    }
#undef LOAD_O

    // ---- epilogue: bias + residual (fp32), write (B,C,N) ----
#pragma unroll
    for (int j = 0; j < 4; j++) {
        int jj0 = j0 + wn*32 + 8*j + 2*q;
#pragma unroll
        for (int col = 0; col < 2; col++) {
            int jj = jj0 + col;
            float bj = bias[jj];
            size_t rowbase = ((size_t)b*Cc + jj)*Nn;
#pragma unroll
            for (int i = 0; i < 4; i++) {
#pragma unroll
                for (int half = 0; half < 2; half++) {
                    int n = n0 + wm*64 + 16*i + r + 8*half;
                    size_t o = rowbase + n;
                    out[o] = acc[i][j][2*half + col] + bj + resid[o];
                }
            }
        }
    }
}

// ---------------- windowed attention (bf16 mma), 1 block per (head, window) --
__global__ __launch_bounds__(128) void attn_bf()
{
    __shared__ __align__(16) bf16 Qs[64*72];
    __shared__ __align__(16) bf16 Ks[64*72];
    __shared__ __align__(16) bf16 Vs[64*72];

    const int bx  = blockIdx.x;     // 0..4095
    const int h   = bx >> 9;
    const int win = bx & 511;
    const int b   = win >> 6;
    const int w   = win & 63;
    const int wy  = w >> 3, wx = w & 7;
    const int tid = threadIdx.x;
    const int lane = tid & 31, wid = tid >> 5;
    const int grp = lane >> 3, lr = lane & 7;

    // ---- load Q/K/V tiles (64 tokens x 64 d, bf16) ----
    {
        int t  = tid & 63;
        int c2 = tid >> 6;                       // 0/1: which 32-half chunk
        int n_t = ((wy*8 + (t >> 3)) << 6) + wx*8 + (t & 7);
        size_t base = (((size_t)b*NHh + h)*Nn + n_t)*Dd;
#pragma unroll
        for (int u = 0; u < 4; u++) {
            int off = c2*32 + u*8;               // halves
            uint4 qv = *(const uint4*)((const char*)g_Qh + (base + off)*2);
            uint4 kv = *(const uint4*)((const char*)g_Kh + (base + off)*2);
            uint4 vv = *(const uint4*)((const char*)g_Vh + (base + off)*2);
            *(uint4*)((char*)Qs + (t*72 + off)*2) = qv;
            *(uint4*)((char*)Ks + (t*72 + off)*2) = kv;
            *(uint4*)((char*)Vs + (t*72 + off)*2) = vv;
        }
    }
    __syncthreads();

    const int m0 = wid * 16;

    // ---- Q fragments (A operand) ----
    unsigned af[4][4];
#pragma unroll
    for (int kk = 0; kk < 4; kk++) {
        int m  = m0 + ((grp & 1) ? 8 : 0) + lr;
        int ka = (grp & 2) ? 8 : 0;
        ldsm_x4(af[kk][0], af[kk][1], af[kk][2], af[kk][3],
                sptr(Qs + m*72 + kk*16 + ka));
    }

    // ---- S = Q K^T ----
    float s[8][4];
#pragma unroll
    for (int j = 0; j < 8; j++)
#pragma unroll
        for (int c = 0; c < 4; c++) s[j][c] = 0.f;

#pragma unroll
    for (int kk = 0; kk < 4; kk++) {
        unsigned bfr[8][2];
#pragma unroll
        for (int jg = 0; jg < 4; jg++) {
            int n  = jg*16 + ((grp & 2) ? 8 : 0) + lr;
            int ka = (grp & 1) ? 8 : 0;
            ldsm_x4(bfr[jg*2][0], bfr[jg*2][1], bfr[jg*2+1][0], bfr[jg*2+1][1],
                    sptr(Ks + n*72 + kk*16 + ka));
        }
#pragma unroll
        for (int j = 0; j < 8; j++)
            mma_bf16(s[j], af[kk], bfr[j]);
    }

    // ---- scale + bias + softmax (fp32, quad shuffles) ----
    const float* bh = g_bias + (h << 12);
    const int row0 = m0 + (lane >> 2);
    const int col0 = 2 * (lane & 3);
    float mx0 = -1e30f, mx1 = -1e30f;
#pragma unroll
    for (int j = 0; j < 8; j++) {
        float2 b0 = *(const float2*)(bh + row0*64 + 8*j + col0);
        float2 b1 = *(const float2*)(bh + (row0+8)*64 + 8*j + col0);
        s[j][0] = fmaf(s[j][0], 0.125f, b0.x);
        s[j][1] = fmaf(s[j][1], 0.125f, b0.y);
        s[j][2] = fmaf(s[j][2], 0.125f, b1.x);
        s[j][3] = fmaf(s[j][3], 0.125f, b1.y);
        mx0 = fmaxf(mx0, fmaxf(s[j][0], s[j][1]));
        mx1 = fmaxf(mx1, fmaxf(s[j][2], s[j][3]));
    }
    mx0 = fmaxf(mx0, __shfl_xor_sync(0xffffffffu, mx0, 1));
    mx0 = fmaxf(mx0, __shfl_xor_sync(0xffffffffu, mx0, 2));
    mx1 = fmaxf(mx1, __shfl_xor_sync(0xffffffffu, mx1, 1));
    mx1 = fmaxf(mx1, __shfl_xor_sync(0xffffffffu, mx1, 2));

    float sum0 = 0.f, sum1 = 0.f;
#pragma unroll
    for (int j = 0; j < 8; j++) {
        s[j][0] = __expf(s[j][0] - mx0);
        s[j][1] = __expf(s[j][1] - mx0);
        s[j][2] = __expf(s[j][2] - mx1);
        s[j][3] = __expf(s[j][3] - mx1);
        sum0 += s[j][0] + s[j][1];
        sum1 += s[j][2] + s[j][3];
    }
    sum0 += __shfl_xor_sync(0xffffffffu, sum0, 1);
    sum0 += __shfl_xor_sync(0xffffffffu, sum0, 2);
    sum1 += __shfl_xor_sync(0xffffffffu, sum1, 1);
    sum1 += __shfl_xor_sync(0xffffffffu, sum1, 2);
    float inv0 = 1.f / sum0, inv1 = 1.f / sum1;

    // ---- O = P V (P from S-frags packed as A-frags; V via ldmatrix.trans) ----
    float o[8][4];
#pragma unroll
    for (int j = 0; j < 8; j++)
#pragma unroll
        for (int c = 0; c < 4; c++) o[j][c] = 0.f;

#pragma unroll
    for (int kk = 0; kk < 4; kk++) {
        unsigned pa[4];
        pa[0] = packbf(s[2*kk  ][0], s[2*kk  ][1]);
        pa[1] = packbf(s[2*kk  ][2], s[2*kk  ][3]);
        pa[2] = packbf(s[2*kk+1][0], s[2*kk+1][1]);
        pa[3] = packbf(s[2*kk+1][2], s[2*kk+1][3]);
        unsigned vb[8][2];
#pragma unroll
        for (int jg = 0; jg < 4; jg++) {
            int rowk = kk*16 + ((grp & 1) ? 8 : 0) + lr;
            int cold = jg*16 + ((grp & 2) ? 8 : 0);
            ldsm_x4t(vb[jg*2][0], vb[jg*2][1], vb[jg*2+1][0], vb[jg*2+1][1],
                     sptr(Vs + rowk*72 + cold));
        }
#pragma unroll
        for (int j = 0; j < 8; j++)
            mma_bf16(o[j], pa, vb[j]);
    }

    // ---- store to g_AOh (B,N,C) bf16 ----
    {
        int tA = row0, tB = row0 + 8;
        int nA = ((wy*8 + (tA >> 3)) << 6) + wx*8 + (tA & 7);
        int nB = ((wy*8 + (tB >> 3)) << 6) + wx*8 + (tB & 7);
        size_t baseA = ((size_t)b*Nn + nA)*Cc + (h << 6);
        size_t baseB = ((size_t)b*Nn + nB)*Cc + (h << 6);
#pragma unroll
        for (int j = 0; j < 8; j++) {
            int d = 8*j + col0;
            *(__nv_bfloat162*)&g_AOh[baseA + d] =
                __floats2bfloat162_rn(o[j][0]*inv0, o[j][1]*inv0);
            *(__nv_bfloat162*)&g_AOh[baseB + d] =
                __floats2bfloat162_rn(o[j][2]*inv1, o[j][3]*inv1);
        }
    }
}

// ---------------- host side ----------------
extern "C" void kernel_launch(void* const* d_in, const int* in_sizes, int n_in,
                              void* d_out, int out_size)
{
    const float* q    = (const float*)d_in[0];
    const float* kv   = (const float*)d_in[1];
    const float* gq   = (const float*)d_in[2];
    const float* bqln = (const float*)d_in[3];
    const float* gkv  = (const float*)d_in[4];
    const float* bkvln= (const float*)d_in[5];
    const float* Wq   = (const float*)d_in[6];
    const float* bq   = (const float*)d_in[7];
    const float* Wk   = (const float*)d_in[8];
    const float* bk   = (const float*)d_in[9];
    const float* Wv   = (const float*)d_in[10];
    const float* bv   = (const float*)d_in[11];
    const float* Wo   = (const float*)d_in[12];
    const float* bo   = (const float*)d_in[13];
    const float* tbl  = (const float*)d_in[14];
    float* out = (float*)d_out;

    void* p;
    cudaGetSymbolAddress(&p, g_qn);   float* qn  = (float*)p;
    cudaGetSymbolAddress(&p, g_qnh);  bf16* qnh  = (bf16*)p;
    cudaGetSymbolAddress(&p, g_kvnh); bf16* kvnh = (bf16*)p;
    cudaGetSymbolAddress(&p, g_Wh);   bf16* Wh   = (bf16*)p;
    cudaGetSymbolAddress(&p, g_Qh);   bf16* Qb   = (bf16*)p;
    cudaGetSymbolAddress(&p, g_Kh);   bf16* Kb   = (bf16*)p;
    cudaGetSymbolAddress(&p, g_Vh);   bf16* Vb   = (bf16*)p;
    cudaGetSymbolAddress(&p, g_AOh);  bf16* AO   = (bf16*)p;

    const int SMEM_QKV = (3*32*128 + 3*128*40) * 2;   // 54912 B
    const int SMEM_O   = (6*128*40) * 2;              // 61440 B
    static int smem_set = 0;
    if (!smem_set) {
        cudaFuncSetAttribute(gemm_qkv_bf, cudaFuncAttributeMaxDynamicSharedMemorySize, SMEM_QKV);
        cudaFuncSetAttribute(gemm_o_bf,   cudaFuncAttributeMaxDynamicSharedMemorySize, SMEM_O);
        smem_set = 1;
    }

    // weight conversion (bf16), one launch for all 4 matrices
    wcvt_kernel<<<Cc*Cc/1024, 1024>>>(Wq, Wk, Wv, Wo);

    // layernorms
    ln_kernel<true ><<<256, 128>>>(q,  gq,  bqln,  qn, qnh);
    ln_kernel<false><<<256, 128>>>(kv, gkv, bkvln, qn, kvnh);

    // rope + bias tables
    rope_kernel<<<(Nn*32)/256, 256>>>();
    bias_kernel<<<(NHh*64*64)/256, 256>>>(tbl);

    // merged Q/K/V projections (rope fused for Q and K)
    gemm_qkv_bf<<<dim3(256, 12), 256, SMEM_QKV>>>(qnh, kvnh, bq, bk, bv, Qb, Kb, Vb);

    // windowed attention
    attn_bf<<<NHh * Bb * 64, 128>>>();

    // output projection + bias + residual -> (B,C,H,W)
    gemm_o_bf<<<dim3(256, 4), 256, SMEM_O>>>(AO, Wh + 3*Cc*Cc, bo, qn, out);
}

// round 7
// speedup vs baseline: 4.8239x; 1.1240x over previous
#include <cuda_runtime.h>
#include <cuda_bf16.h>
#include <math.h>

#define Bb   8
#define Cc   512
#define Nn   4096
#define NHh  8
#define Dd   64
#define EPSf 1e-5f

typedef __nv_bfloat16 bf16;

// ---------------- scratch (device globals; no allocation) ----------------
__device__ float g_qn  [Bb*Cc*Nn];        // layernormed q, (B,C,N) fp32 (residual)
__device__ bf16  g_qnt [Bb*Nn*Cc];        // layernormed q, token-major (B,N,C) bf16
__device__ bf16  g_kvnt[Bb*Nn*Cc];        // layernormed kv, token-major bf16
__device__ bf16  g_Wh  [4*Cc*Cc];         // Wq,Wk,Wv,Wo in bf16
__device__ bf16  g_Qh  [Bb*NHh*Nn*Dd];    // (B,NH,N,D) rope applied
__device__ bf16  g_Kh  [Bb*NHh*Nn*Dd];
__device__ bf16  g_Vh  [Bb*NHh*Nn*Dd];
__device__ bf16  g_AOh [Bb*Nn*Cc];        // attention out, (B,N,C)
__device__ float g_sin [Nn*32];
__device__ float g_cos [Nn*32];
__device__ float g_bias[NHh*64*64];       // (NH, Ws, Ws)

// ---------------- helpers ----------------
__device__ __forceinline__ unsigned sptr(const void* p) {
    return (unsigned)__cvta_generic_to_shared(p);
}
#define CP16(d, s)  asm volatile("cp.async.cg.shared.global [%0], [%1], 16;" :: "r"(d), "l"(s))
#define CP_COMMIT() asm volatile("cp.async.commit_group;")
#define CP_WAIT(n)  asm volatile("cp.async.wait_group %0;" :: "n"(n))

__device__ __forceinline__ void ldsm_x4(unsigned& r0, unsigned& r1, unsigned& r2, unsigned& r3, unsigned a) {
    asm volatile("ldmatrix.sync.aligned.m8n8.x4.shared.b16 {%0,%1,%2,%3}, [%4];"
                 : "=r"(r0), "=r"(r1), "=r"(r2), "=r"(r3) : "r"(a));
}
__device__ __forceinline__ void ldsm_x4t(unsigned& r0, unsigned& r1, unsigned& r2, unsigned& r3, unsigned a) {
    asm volatile("ldmatrix.sync.aligned.m8n8.x4.trans.shared.b16 {%0,%1,%2,%3}, [%4];"
                 : "=r"(r0), "=r"(r1), "=r"(r2), "=r"(r3) : "r"(a));
}
__device__ __forceinline__ void mma_bf16(float* c, const unsigned* a, const unsigned* b) {
    asm volatile(
        "mma.sync.aligned.m16n8k16.row.col.f32.bf16.bf16.f32 "
        "{%0,%1,%2,%3}, {%4,%5,%6,%7}, {%8,%9}, {%0,%1,%2,%3};"
        : "+f"(c[0]), "+f"(c[1]), "+f"(c[2]), "+f"(c[3])
        : "r"(a[0]), "r"(a[1]), "r"(a[2]), "r"(a[3]), "r"(b[0]), "r"(b[1]));
}
__device__ __forceinline__ unsigned packbf(float lo, float hi) {
    unsigned d; asm("cvt.rn.bf16x2.f32 %0, %1, %2;" : "=r"(d) : "f"(hi), "f"(lo)); return d;
}

// ============ prep: weight cvt + rope table + bias table, one launch ========
__global__ __launch_bounds__(256) void prep_kernel(const float* __restrict__ w0,
                                                   const float* __restrict__ w1,
                                                   const float* __restrict__ w2,
                                                   const float* __restrict__ w3,
                                                   const float* __restrict__ table)
{
    int blk = blockIdx.x;
    if (blk < 1024) {                        // wcvt: 1024*256 = 262144 = Cc*Cc
        int i = blk * 256 + threadIdx.x;
        g_Wh[0*Cc*Cc + i] = __float2bfloat16_rn(w0[i]);
        g_Wh[1*Cc*Cc + i] = __float2bfloat16_rn(w1[i]);
        g_Wh[2*Cc*Cc + i] = __float2bfloat16_rn(w2[i]);
        g_Wh[3*Cc*Cc + i] = __float2bfloat16_rn(w3[i]);
    } else if (blk < 1536) {                 // rope: 512*256 = 131072 = Nn*32
        int i = (blk - 1024) * 256 + threadIdx.x;
        int n = i >> 5, k = i & 31;
        float invf = exp2f(-(float)k * (13.287712379549449f / 32.0f));
        float ang  = (float)n * invf;
        float sv, cv;  sincosf(ang, &sv, &cv);
        g_sin[i] = sv;  g_cos[i] = cv;
    } else {                                 // bias: 128*256 = 32768 = NH*4096
        int i = (blk - 1536) * 256 + threadIdx.x;
        int h  = i >> 12;
        int qi = (i >> 6) & 63, ki = i & 63;
        int dh = (qi >> 3) - (ki >> 3) + 7;
        int dw = (qi & 7)  - (ki & 7)  + 7;
        g_bias[i] = table[(dh * 15 + dw) * NHh + h];
    }
}

// ====== layernorm: 32 tokens x 512 C per block, smem transpose ======
// single global read; outputs token-major bf16 (+ channel-major fp32 for q).
template<bool F32OUT>
__global__ __launch_bounds__(256) void ln_kernel(const float* __restrict__ x,
                                                 const float* __restrict__ g,
                                                 const float* __restrict__ bt,
                                                 float* __restrict__ yf,
                                                 bf16* __restrict__ yh)
{
    extern __shared__ float sm[];
    float* sx  = sm;                  // [512][33]
    float* ps  = sm + 512*33;         // [8][32]
    float* ps2 = ps + 256;            // [8][32]
    float* smu = ps2 + 256;           // [32]
    float* sin_ = smu + 32;           // [32] inv

    const int blk = blockIdx.x;       // 0..1023
    const int b   = blk >> 7;
    const int n0  = (blk & 127) * 32;
    const int tid = threadIdx.x;
    const int t   = tid & 31;         // token within tile
    const int cp  = tid >> 5;         // 0..7 c-partition

    const float* xb = x + (size_t)b*Cc*Nn + n0;
    float s = 0.f, s2 = 0.f;
#pragma unroll 8
    for (int it = 0; it < 64; it++) {
        int c = it*8 + cp;
        float v = xb[(size_t)c*Nn + t];
        sx[c*33 + t] = v;
        s += v;  s2 = fmaf(v, v, s2);
    }
    ps[cp*32 + t] = s;  ps2[cp*32 + t] = s2;
    __syncthreads();
    if (tid < 32) {
        float a = 0.f, a2 = 0.f;
#pragma unroll
        for (int k = 0; k < 8; k++) { a += ps[k*32 + tid]; a2 += ps2[k*32 + tid]; }
        float mu  = a * (1.f/Cc);
        float var = a2 * (1.f/Cc) - mu*mu;
        smu[tid]  = mu;
        sin_[tid] = rsqrtf(var + EPSf);
    }
    __syncthreads();

    const float mu = smu[t], inv = sin_[t];
    float* yfb = F32OUT ? (yf + (size_t)b*Cc*Nn + n0) : nullptr;
#pragma unroll 8
    for (int it = 0; it < 64; it++) {
        int c = it*8 + cp;
        float o = (sx[c*33 + t] - mu) * inv * g[c] + bt[c];
        sx[c*33 + t] = o;
        if (F32OUT) yfb[(size_t)c*Nn + t] = o;
    }
    __syncthreads();

    // token-major bf16 write: thread = (token=tid&31, cbase=(tid>>5)*64)
    {
        int tok = tid & 31, cb = (tid >> 5) * 64;
        union { uint4 q[8]; unsigned u[32]; } buf;
#pragma unroll
        for (int i = 0; i < 32; i++) {
            float v0 = sx[(cb + 2*i    )*33 + tok];
            float v1 = sx[(cb + 2*i + 1)*33 + tok];
            buf.u[i] = packbf(v0, v1);
        }
        uint4* dst = (uint4*)(yh + ((size_t)b*Nn + n0 + tok)*Cc + cb);
#pragma unroll
        for (int i = 0; i < 8; i++) dst[i] = buf.q[i];
    }
}

// ================= bf16 GEMM (NT): merged Q/K/V projections ==================
// blockIdx.y 0..11: seg = y>>2 (Q/K/V), j0 = (y&3)*128.
// A token-major bf16 (B,N,C) [m][k]; W bf16 [n][k]. Out (B,NH,N,D) bf16,
// fused RoPE for Q/K. Block 128x128, BK=32, 3-stage cp.async, 8 warps.
__global__ __launch_bounds__(256, 2) void gemm_qkv_bf(const bf16* __restrict__ Aq,
                                                      const bf16* __restrict__ Akv,
                                                      const float* __restrict__ bq,
                                                      const float* __restrict__ bk,
                                                      const float* __restrict__ bv,
                                                      bf16* __restrict__ outQ,
                                                      bf16* __restrict__ outK,
                                                      bf16* __restrict__ outV)
{
    extern __shared__ __align__(16) bf16 smraw[];
    bf16* As = smraw;                 // 3 x 128*40
    bf16* Bs = smraw + 3*128*40;      // 3 x 128*40

    const int seg = blockIdx.y >> 2;            // 0=Q 1=K 2=V
    const bf16*  A    = seg ? Akv : Aq;
    const bf16*  W    = g_Wh + (size_t)seg*Cc*Cc;
    const float* bias = (seg == 0) ? bq : (seg == 1) ? bk : bv;
    bf16*        out  = (seg == 0) ? outQ : (seg == 1) ? outK : outV;
    const bool   rope = (seg < 2);
    const int j0 = (blockIdx.y & 3) * 128;

    const int t0 = blockIdx.x * 128;
    const int b  = t0 >> 12;
    const int n0 = t0 & 4095;
    const int tid = threadIdx.x;
    const int lane = tid & 31, wid = tid >> 5;
    const int wm = wid & 1, wn = wid >> 1;
    const int r = lane >> 2, q = lane & 3;
    const int grp = lane >> 3, lr = lane & 7;

    float acc[4][4][4];
#pragma unroll
    for (int i = 0; i < 4; i++)
#pragma unroll
        for (int j = 0; j < 4; j++)
#pragma unroll
            for (int k = 0; k < 4; k++) acc[i][j][k] = 0.f;

#define LOAD_QKV(S, BUF)                                                        \
    {                                                                           \
        bf16* Ad = As + (BUF)*5120;                                             \
        bf16* Bd = Bs + (BUF)*5120;                                             \
        int c0 = (S)*32;                                                        \
        _Pragma("unroll")                                                       \
        for (int u = 0; u < 2; u++) {                                           \
            int ac = tid*2 + u;                                                 \
            int m = ac >> 2, kc = ac & 3;                                       \
            CP16(sptr(Ad + m*40 + kc*8),                                        \
                 A + (size_t)(t0+m)*Cc + c0 + kc*8);                            \
        }                                                                       \
        _Pragma("unroll")                                                       \
        for (int u = 0; u < 2; u++) {                                           \
            int bc = tid*2 + u;                                                 \
            int n = bc >> 2, kc = bc & 3;                                       \
            CP16(sptr(Bd + n*40 + kc*8),                                        \
                 W + (size_t)(j0+n)*Cc + c0 + kc*8);                            \
        }                                                                       \
    }

    LOAD_QKV(0, 0); CP_COMMIT();
    LOAD_QKV(1, 1); CP_COMMIT();

#pragma unroll 1
    for (int s = 0; s < 16; s++) {
        if (s < 15) { CP_WAIT(1); } else { CP_WAIT(0); }
        __syncthreads();
        if (s < 14) { LOAD_QKV(s+2, (s+2)%3); CP_COMMIT(); }

        const bf16* Ac = As + (s%3)*5120;
        const bf16* Bc = Bs + (s%3)*5120;
#pragma unroll
        for (int kk = 0; kk < 2; kk++) {
            unsigned af[4][4], bfr[4][2];
#pragma unroll
            for (int i = 0; i < 4; i++) {
                int m  = wm*64 + 16*i + ((grp & 1) ? 8 : 0) + lr;
                int ka = (grp & 2) ? 8 : 0;
                ldsm_x4(af[i][0], af[i][1], af[i][2], af[i][3],
                        sptr(Ac + m*40 + kk*16 + ka));
            }
#pragma unroll
            for (int jg = 0; jg < 2; jg++) {
                int n = wn*32 + jg*16 + ((grp & 2) ? 8 : 0) + lr;
                int ka = (grp & 1) ? 8 : 0;
                ldsm_x4(bfr[jg*2][0], bfr[jg*2][1], bfr[jg*2+1][0], bfr[jg*2+1][1],
                        sptr(Bc + n*40 + kk*16 + ka));
            }
#pragma unroll
            for (int i = 0; i < 4; i++)
#pragma unroll
                for (int j = 0; j < 4; j++)
                    mma_bf16(acc[i][j], af[i], bfr[j]);
        }
    }
#undef LOAD_QKV

    // ---- epilogue: bias (+ RoPE, fp32), store bf16 ----
#pragma unroll
    for (int i = 0; i < 4; i++) {
        int ntok = n0 + wm*64 + 16*i + r;
#pragma unroll
        for (int j = 0; j < 4; j++) {
            int jj = j0 + wn*32 + 8*j + 2*q;
            int hh = jj >> 6;
            int d  = jj & 63;                  // even
            float bv0 = bias[jj], bv1 = bias[jj+1];
#pragma unroll
            for (int half = 0; half < 2; half++) {
                int n = ntok + 8*half;
                float v0 = acc[i][j][2*half+0] + bv0;
                float v1 = acc[i][j][2*half+1] + bv1;
                float x, y;
                if (rope) {
                    int p = (n << 5) + (d >> 1);
                    float sv = g_sin[p], cv = g_cos[p];
                    x = v0*cv - v1*sv;
                    y = v0*sv + v1*cv;
                } else { x = v0; y = v1; }
                *(__nv_bfloat162*)&out[(((size_t)b*NHh + hh)*Nn + n)*Dd + d] =
                    __floats2bfloat162_rn(x, y);
            }
        }
    }
}

// ================= bf16 GEMM (NT): output projection ==================
// A = g_AOh (B,N,C) bf16 [m][k]; W = Wo bf16 [n][k];
// out fp32 (B,C,N) = A@Wo^T + bo + resid(fp32). 3-stage pipeline.
__global__ __launch_bounds__(256, 2) void gemm_o_bf(const bf16* __restrict__ A,
                                                    const bf16* __restrict__ W,
                                                    const float* __restrict__ bias,
                                                    const float* __restrict__ resid,
                                                    float* __restrict__ out)
{
    extern __shared__ __align__(16) bf16 smraw[];
    bf16* As = smraw;                 // 3 x 128*40
    bf16* Bs = smraw + 3*128*40;      // 3 x 128*40

    const int t0 = blockIdx.x * 128;
    const int b  = t0 >> 12;
    const int n0 = t0 & 4095;
    const int j0 = blockIdx.y * 128;
    const int tid = threadIdx.x;
    const int lane = tid & 31, wid = tid >> 5;
    const int wm = wid & 1, wn = wid >> 1;
    const int r = lane >> 2, q = lane & 3;
    const int grp = lane >> 3, lr = lane & 7;

    float acc[4][4][4];
#pragma unroll
    for (int i = 0; i < 4; i++)
#pragma unroll
        for (int j = 0; j < 4; j++)
#pragma unroll
            for (int k = 0; k < 4; k++) acc[i][j][k] = 0.f;

#define LOAD_O(S, BUF)                                                          \
    {                                                                           \
        bf16* Ad = As + (BUF)*5120;                                             \
        bf16* Bd = Bs + (BUF)*5120;                                             \
        int c0 = (S)*32;                                                        \
        _Pragma("unroll")                                                       \
        for (int u = 0; u < 2; u++) {                                           \
            int ac = tid*2 + u;                                                 \
            int m = ac >> 2, kc = ac & 3;                                       \
            CP16(sptr(Ad + m*40 + kc*8),                                        \
                 A + (size_t)(t0+m)*Cc + c0 + kc*8);                            \
        }                                                                       \
        _Pragma("unroll")                                                       \
        for (int u = 0; u < 2; u++) {                                           \
            int bc = tid*2 + u;                                                 \
            int n = bc >> 2, kc = bc & 3;                                       \
            CP16(sptr(Bd + n*40 + kc*8),                                        \
                 W + (size_t)(j0+n)*Cc + c0 + kc*8);                            \
        }                                                                       \
    }

    LOAD_O(0, 0); CP_COMMIT();
    LOAD_O(1, 1); CP_COMMIT();

#pragma unroll 1
    for (int s = 0; s < 16; s++) {
        if (s < 15) { CP_WAIT(1); } else { CP_WAIT(0); }
        __syncthreads();
        if (s < 14) { LOAD_O(s+2, (s+2)%3); CP_COMMIT(); }

        const bf16* Ac = As + (s%3)*5120;
        const bf16* Bc = Bs + (s%3)*5120;
#pragma unroll
        for (int kk = 0; kk < 2; kk++) {
            unsigned af[4][4], bfr[4][2];
#pragma unroll
            for (int i = 0; i < 4; i++) {
                int m  = wm*64 + 16*i + ((grp & 1) ? 8 : 0) + lr;
                int ka = (grp & 2) ? 8 : 0;
                ldsm_x4(af[i][0], af[i][1], af[i][2], af[i][3],
                        sptr(Ac + m*40 + kk*16 + ka));
            }
#pragma unroll
            for (int jg = 0; jg < 2; jg++) {
                int n = wn*32 + jg*16 + ((grp & 2) ? 8 : 0) + lr;
                int ka = (grp & 1) ? 8 : 0;
                ldsm_x4(bfr[jg*2][0], bfr[jg*2][1], bfr[jg*2+1][0], bfr[jg*2+1][1],
                        sptr(Bc + n*40 + kk*16 + ka));
            }
#pragma unroll
            for (int i = 0; i < 4; i++)
#pragma unroll
                for (int j = 0; j < 4; j++)
                    mma_bf16(acc[i][j], af[i], bfr[j]);
        }
    }
#undef LOAD_O

    // ---- epilogue: bias + residual (fp32), write (B,C,N) ----
#pragma unroll
    for (int j = 0; j < 4; j++) {
        int jj0 = j0 + wn*32 + 8*j + 2*q;
#pragma unroll
        for (int col = 0; col < 2; col++) {
            int jj = jj0 + col;
            float bj = bias[jj];
            size_t rowbase = ((size_t)b*Cc + jj)*Nn;
#pragma unroll
            for (int i = 0; i < 4; i++) {
#pragma unroll
                for (int half = 0; half < 2; half++) {
                    int n = n0 + wm*64 + 16*i + r + 8*half;
                    size_t o = rowbase + n;
                    out[o] = acc[i][j][2*half + col] + bj + resid[o];
                }
            }
        }
    }
}

// ---------------- windowed attention (bf16 mma), 1 block per (head, window) --
__global__ __launch_bounds__(128) void attn_bf()
{
    __shared__ __align__(16) bf16 Qs[64*72];
    __shared__ __align__(16) bf16 Ks[64*72];
    __shared__ __align__(16) bf16 Vs[64*72];

    const int bx  = blockIdx.x;     // 0..4095
    const int h   = bx >> 9;
    const int win = bx & 511;
    const int b   = win >> 6;
    const int w   = win & 63;
    const int wy  = w >> 3, wx = w & 7;
    const int tid = threadIdx.x;
    const int lane = tid & 31, wid = tid >> 5;
    const int grp = lane >> 3, lr = lane & 7;

    {
        int t  = tid & 63;
        int c2 = tid >> 6;
        int n_t = ((wy*8 + (t >> 3)) << 6) + wx*8 + (t & 7);
        size_t base = (((size_t)b*NHh + h)*Nn + n_t)*Dd;
#pragma unroll
        for (int u = 0; u < 4; u++) {
            int off = c2*32 + u*8;
            uint4 qv = *(const uint4*)((const char*)g_Qh + (base + off)*2);
            uint4 kv = *(const uint4*)((const char*)g_Kh + (base + off)*2);
            uint4 vv = *(const uint4*)((const char*)g_Vh + (base + off)*2);
            *(uint4*)((char*)Qs + (t*72 + off)*2) = qv;
            *(uint4*)((char*)Ks + (t*72 + off)*2) = kv;
            *(uint4*)((char*)Vs + (t*72 + off)*2) = vv;
        }
    }
    __syncthreads();

    const int m0 = wid * 16;

    unsigned af[4][4];
#pragma unroll
    for (int kk = 0; kk < 4; kk++) {
        int m  = m0 + ((grp & 1) ? 8 : 0) + lr;
        int ka = (grp & 2) ? 8 : 0;
        ldsm_x4(af[kk][0], af[kk][1], af[kk][2], af[kk][3],
                sptr(Qs + m*72 + kk*16 + ka));
    }

    float s[8][4];
#pragma unroll
    for (int j = 0; j < 8; j++)
#pragma unroll
        for (int c = 0; c < 4; c++) s[j][c] = 0.f;

#pragma unroll
    for (int kk = 0; kk < 4; kk++) {
        unsigned bfr[8][2];
#pragma unroll
        for (int jg = 0; jg < 4; jg++) {
            int n  = jg*16 + ((grp & 2) ? 8 : 0) + lr;
            int ka = (grp & 1) ? 8 : 0;
            ldsm_x4(bfr[jg*2][0], bfr[jg*2][1], bfr[jg*2+1][0], bfr[jg*2+1][1],
                    sptr(Ks + n*72 + kk*16 + ka));
        }
#pragma unroll
        for (int j = 0; j < 8; j++)
            mma_bf16(s[j], af[kk], bfr[j]);
    }

    const float* bh = g_bias + (h << 12);
    const int row0 = m0 + (lane >> 2);
    const int col0 = 2 * (lane & 3);
    float mx0 = -1e30f, mx1 = -1e30f;
#pragma unroll
    for (int j = 0; j < 8; j++) {
        float2 b0 = *(const float2*)(bh + row0*64 + 8*j + col0);
        float2 b1 = *(const float2*)(bh + (row0+8)*64 + 8*j + col0);
        s[j][0] = fmaf(s[j][0], 0.125f, b0.x);
        s[j][1] = fmaf(s[j][1], 0.125f, b0.y);
        s[j][2] = fmaf(s[j][2], 0.125f, b1.x);
        s[j][3] = fmaf(s[j][3], 0.125f, b1.y);
        mx0 = fmaxf(mx0, fmaxf(s[j][0], s[j][1]));
        mx1 = fmaxf(mx1, fmaxf(s[j][2], s[j][3]));
    }
    mx0 = fmaxf(mx0, __shfl_xor_sync(0xffffffffu, mx0, 1));
    mx0 = fmaxf(mx0, __shfl_xor_sync(0xffffffffu, mx0, 2));
    mx1 = fmaxf(mx1, __shfl_xor_sync(0xffffffffu, mx1, 1));
    mx1 = fmaxf(mx1, __shfl_xor_sync(0xffffffffu, mx1, 2));

    float sum0 = 0.f, sum1 = 0.f;
#pragma unroll
    for (int j = 0; j < 8; j++) {
        s[j][0] = __expf(s[j][0] - mx0);
        s[j][1] = __expf(s[j][1] - mx0);
        s[j][2] = __expf(s[j][2] - mx1);
        s[j][3] = __expf(s[j][3] - mx1);
        sum0 += s[j][0] + s[j][1];
        sum1 += s[j][2] + s[j][3];
    }
    sum0 += __shfl_xor_sync(0xffffffffu, sum0, 1);
    sum0 += __shfl_xor_sync(0xffffffffu, sum0, 2);
    sum1 += __shfl_xor_sync(0xffffffffu, sum1, 1);
    sum1 += __shfl_xor_sync(0xffffffffu, sum1, 2);
    float inv0 = 1.f / sum0, inv1 = 1.f / sum1;

    float o[8][4];
#pragma unroll
    for (int j = 0; j < 8; j++)
#pragma unroll
        for (int c = 0; c < 4; c++) o[j][c] = 0.f;

#pragma unroll
    for (int kk = 0; kk < 4; kk++) {
        unsigned pa[4];
        pa[0] = packbf(s[2*kk  ][0], s[2*kk  ][1]);
        pa[1] = packbf(s[2*kk  ][2], s[2*kk  ][3]);
        pa[2] = packbf(s[2*kk+1][0], s[2*kk+1][1]);
        pa[3] = packbf(s[2*kk+1][2], s[2*kk+1][3]);
        unsigned vb[8][2];
#pragma unroll
        for (int jg = 0; jg < 4; jg++) {
            int rowk = kk*16 + ((grp & 1) ? 8 : 0) + lr;
            int cold = jg*16 + ((grp & 2) ? 8 : 0);
            ldsm_x4t(vb[jg*2][0], vb[jg*2][1], vb[jg*2+1][0], vb[jg*2+1][1],
                     sptr(Vs + rowk*72 + cold));
        }
#pragma unroll
        for (int j = 0; j < 8; j++)
            mma_bf16(o[j], pa, vb[j]);
    }

    {
        int tA = row0, tB = row0 + 8;
        int nA = ((wy*8 + (tA >> 3)) << 6) + wx*8 + (tA & 7);
        int nB = ((wy*8 + (tB >> 3)) << 6) + wx*8 + (tB & 7);
        size_t baseA = ((size_t)b*Nn + nA)*Cc + (h << 6);
        size_t baseB = ((size_t)b*Nn + nB)*Cc + (h << 6);
#pragma unroll
        for (int j = 0; j < 8; j++) {
            int d = 8*j + col0;
            *(__nv_bfloat162*)&g_AOh[baseA + d] =
                __floats2bfloat162_rn(o[j][0]*inv0, o[j][1]*inv0);
            *(__nv_bfloat162*)&g_AOh[baseB + d] =
                __floats2bfloat162_rn(o[j][2]*inv1, o[j][3]*inv1);
        }
    }
}

// ---------------- host side ----------------
extern "C" void kernel_launch(void* const* d_in, const int* in_sizes, int n_in,
                              void* d_out, int out_size)
{
    const float* q    = (const float*)d_in[0];
    const float* kv   = (const float*)d_in[1];
    const float* gq   = (const float*)d_in[2];
    const float* bqln = (const float*)d_in[3];
    const float* gkv  = (const float*)d_in[4];
    const float* bkvln= (const float*)d_in[5];
    const float* Wq   = (const float*)d_in[6];
    const float* bq   = (const float*)d_in[7];
    const float* Wk   = (const float*)d_in[8];
    const float* bk   = (const float*)d_in[9];
    const float* Wv   = (const float*)d_in[10];
    const float* bv   = (const float*)d_in[11];
    const float* Wo   = (const float*)d_in[12];
    const float* bo   = (const float*)d_in[13];
    const float* tbl  = (const float*)d_in[14];
    float* out = (float*)d_out;

    void* p;
    cudaGetSymbolAddress(&p, g_qn);   float* qn   = (float*)p;
    cudaGetSymbolAddress(&p, g_qnt);  bf16* qnt   = (bf16*)p;
    cudaGetSymbolAddress(&p, g_kvnt); bf16* kvnt  = (bf16*)p;
    cudaGetSymbolAddress(&p, g_Wh);   bf16* Wh    = (bf16*)p;
    cudaGetSymbolAddress(&p, g_Qh);   bf16* Qb    = (bf16*)p;
    cudaGetSymbolAddress(&p, g_Kh);   bf16* Kb    = (bf16*)p;
    cudaGetSymbolAddress(&p, g_Vh);   bf16* Vb    = (bf16*)p;
    cudaGetSymbolAddress(&p, g_AOh);  bf16* AO    = (bf16*)p;

    const int SMEM_LN = (512*33 + 512 + 64) * 4;     // 69888 B
    const int SMEM_G  = (6*128*40) * 2;              // 61440 B
    static int smem_set = 0;
    if (!smem_set) {
        cudaFuncSetAttribute(ln_kernel<true>,  cudaFuncAttributeMaxDynamicSharedMemorySize, SMEM_LN);
        cudaFuncSetAttribute(ln_kernel<false>, cudaFuncAttributeMaxDynamicSharedMemorySize, SMEM_LN);
        cudaFuncSetAttribute(gemm_qkv_bf,      cudaFuncAttributeMaxDynamicSharedMemorySize, SMEM_G);
        cudaFuncSetAttribute(gemm_o_bf,        cudaFuncAttributeMaxDynamicSharedMemorySize, SMEM_G);
        smem_set = 1;
    }

    // 0: weight cvt + rope + bias tables (one launch)
    prep_kernel<<<1664, 256>>>(Wq, Wk, Wv, Wo, tbl);

    // 1,2: layernorms (token-major bf16 out; q also fp32 channel-major)
    ln_kernel<true ><<<1024, 256, SMEM_LN>>>(q,  gq,  bqln,  qn, qnt);
    ln_kernel<false><<<1024, 256, SMEM_LN>>>(kv, gkv, bkvln, qn, kvnt);

    // 3: merged Q/K/V projections (rope fused for Q and K)
    gemm_qkv_bf<<<dim3(256, 12), 256, SMEM_G>>>(qnt, kvnt, bq, bk, bv, Qb, Kb, Vb);

    // 4: windowed attention
    attn_bf<<<NHh * Bb * 64, 128>>>();

    // 5: output projection + bias + residual -> (B,C,H,W)
    gemm_o_bf<<<dim3(256, 4), 256, SMEM_G>>>(AO, Wh + 3*Cc*Cc, bo, qn, out);
}

// round 8
// speedup vs baseline: 5.3928x; 1.1179x over previous
#include <cuda_runtime.h>
#include <cuda_bf16.h>
#include <math.h>

#define Bb   8
#define Cc   512
#define Nn   4096
#define NHh  8
#define Dd   64
#define EPSf 1e-5f

typedef __nv_bfloat16 bf16;

// ---------------- scratch (device globals; no allocation) ----------------
__device__ float g_qn  [Bb*Cc*Nn];        // layernormed q, (B,C,N) fp32 (residual)
__device__ bf16  g_qnt [Bb*Nn*Cc];        // layernormed q, token-major (B,N,C) bf16
__device__ bf16  g_kvnt[Bb*Nn*Cc];        // layernormed kv, token-major bf16
__device__ bf16  g_Wh  [4*Cc*Cc];         // Wq,Wk,Wv,Wo in bf16
__device__ bf16  g_Qh  [Bb*NHh*Nn*Dd];    // (B,NH,N,D) rope applied
__device__ bf16  g_Kh  [Bb*NHh*Nn*Dd];
__device__ bf16  g_Vh  [Bb*NHh*Nn*Dd];
__device__ bf16  g_AOh [Bb*Nn*Cc];        // attention out, (B,N,C)
__device__ float g_sin [Nn*32];
__device__ float g_cos [Nn*32];
__device__ float g_bias[NHh*64*64];       // (NH, Ws, Ws)

// ---------------- helpers ----------------
__device__ __forceinline__ unsigned sptr(const void* p) {
    return (unsigned)__cvta_generic_to_shared(p);
}
#define CP16(d, s)  asm volatile("cp.async.cg.shared.global [%0], [%1], 16;" :: "r"(d), "l"(s))
#define CP_COMMIT() asm volatile("cp.async.commit_group;")
#define CP_WAIT(n)  asm volatile("cp.async.wait_group %0;" :: "n"(n))

__device__ __forceinline__ void ldsm_x4(unsigned& r0, unsigned& r1, unsigned& r2, unsigned& r3, unsigned a) {
    asm volatile("ldmatrix.sync.aligned.m8n8.x4.shared.b16 {%0,%1,%2,%3}, [%4];"
                 : "=r"(r0), "=r"(r1), "=r"(r2), "=r"(r3) : "r"(a));
}
__device__ __forceinline__ void ldsm_x4t(unsigned& r0, unsigned& r1, unsigned& r2, unsigned& r3, unsigned a) {
    asm volatile("ldmatrix.sync.aligned.m8n8.x4.trans.shared.b16 {%0,%1,%2,%3}, [%4];"
                 : "=r"(r0), "=r"(r1), "=r"(r2), "=r"(r3) : "r"(a));
}
__device__ __forceinline__ void mma_bf16(float* c, const unsigned* a, const unsigned* b) {
    asm volatile(
        "mma.sync.aligned.m16n8k16.row.col.f32.bf16.bf16.f32 "
        "{%0,%1,%2,%3}, {%4,%5,%6,%7}, {%8,%9}, {%0,%1,%2,%3};"
        : "+f"(c[0]), "+f"(c[1]), "+f"(c[2]), "+f"(c[3])
        : "r"(a[0]), "r"(a[1]), "r"(a[2]), "r"(a[3]), "r"(b[0]), "r"(b[1]));
}
__device__ __forceinline__ unsigned packbf(float lo, float hi) {
    unsigned d; asm("cvt.rn.bf16x2.f32 %0, %1, %2;" : "=r"(d) : "f"(hi), "f"(lo)); return d;
}

// ============ prep: weight cvt + rope table + bias table, one launch ========
__global__ __launch_bounds__(256) void prep_kernel(const float* __restrict__ w0,
                                                   const float* __restrict__ w1,
                                                   const float* __restrict__ w2,
                                                   const float* __restrict__ w3,
                                                   const float* __restrict__ table)
{
    int blk = blockIdx.x;
    if (blk < 1024) {                        // wcvt: 1024*256 = 262144 = Cc*Cc
        int i = blk * 256 + threadIdx.x;
        g_Wh[0*Cc*Cc + i] = __float2bfloat16_rn(w0[i]);
        g_Wh[1*Cc*Cc + i] = __float2bfloat16_rn(w1[i]);
        g_Wh[2*Cc*Cc + i] = __float2bfloat16_rn(w2[i]);
        g_Wh[3*Cc*Cc + i] = __float2bfloat16_rn(w3[i]);
    } else if (blk < 1536) {                 // rope: 512*256 = 131072 = Nn*32
        int i = (blk - 1024) * 256 + threadIdx.x;
        int n = i >> 5, k = i & 31;
        float invf = exp2f(-(float)k * (13.287712379549449f / 32.0f));
        float ang  = (float)n * invf;
        float sv, cv;  sincosf(ang, &sv, &cv);
        g_sin[i] = sv;  g_cos[i] = cv;
    } else {                                 // bias: 128*256 = 32768 = NH*4096
        int i = (blk - 1536) * 256 + threadIdx.x;
        int h  = i >> 12;
        int qi = (i >> 6) & 63, ki = i & 63;
        int dh = (qi >> 3) - (ki >> 3) + 7;
        int dw = (qi & 7)  - (ki & 7)  + 7;
        g_bias[i] = table[(dh * 15 + dw) * NHh + h];
    }
}

// ====== layernorm: 32 tokens x 512 C per block, smem transpose ======
template<bool F32OUT>
__global__ __launch_bounds__(256) void ln_kernel(const float* __restrict__ x,
                                                 const float* __restrict__ g,
                                                 const float* __restrict__ bt,
                                                 float* __restrict__ yf,
                                                 bf16* __restrict__ yh)
{
    extern __shared__ float sm[];
    float* sx  = sm;                  // [512][33]
    float* ps  = sm + 512*33;         // [8][32]
    float* ps2 = ps + 256;            // [8][32]
    float* smu = ps2 + 256;           // [32]
    float* sin_ = smu + 32;           // [32] inv

    const int blk = blockIdx.x;       // 0..1023
    const int b   = blk >> 7;
    const int n0  = (blk & 127) * 32;
    const int tid = threadIdx.x;
    const int t   = tid & 31;
    const int cp  = tid >> 5;

    const float* xb = x + (size_t)b*Cc*Nn + n0;
    float s = 0.f, s2 = 0.f;
#pragma unroll 8
    for (int it = 0; it < 64; it++) {
        int c = it*8 + cp;
        float v = xb[(size_t)c*Nn + t];
        sx[c*33 + t] = v;
        s += v;  s2 = fmaf(v, v, s2);
    }
    ps[cp*32 + t] = s;  ps2[cp*32 + t] = s2;
    __syncthreads();
    if (tid < 32) {
        float a = 0.f, a2 = 0.f;
#pragma unroll
        for (int k = 0; k < 8; k++) { a += ps[k*32 + tid]; a2 += ps2[k*32 + tid]; }
        float mu  = a * (1.f/Cc);
        float var = a2 * (1.f/Cc) - mu*mu;
        smu[tid]  = mu;
        sin_[tid] = rsqrtf(var + EPSf);
    }
    __syncthreads();

    const float mu = smu[t], inv = sin_[t];
    float* yfb = F32OUT ? (yf + (size_t)b*Cc*Nn + n0) : nullptr;
#pragma unroll 8
    for (int it = 0; it < 64; it++) {
        int c = it*8 + cp;
        float o = (sx[c*33 + t] - mu) * inv * g[c] + bt[c];
        sx[c*33 + t] = o;
        if (F32OUT) yfb[(size_t)c*Nn + t] = o;
    }
    __syncthreads();

    {
        int tok = tid & 31, cb = (tid >> 5) * 64;
        union { uint4 q[8]; unsigned u[32]; } buf;
#pragma unroll
        for (int i = 0; i < 32; i++) {
            float v0 = sx[(cb + 2*i    )*33 + tok];
            float v1 = sx[(cb + 2*i + 1)*33 + tok];
            buf.u[i] = packbf(v0, v1);
        }
        uint4* dst = (uint4*)(yh + ((size_t)b*Nn + n0 + tok)*Cc + cb);
#pragma unroll
        for (int i = 0; i < 8; i++) dst[i] = buf.q[i];
    }
}

// ================= bf16 GEMM (NT): merged Q/K/V projections ==================
// BK=64, 3-stage cp.async, 8 stages. smem buffers [128][72] per operand.
__global__ __launch_bounds__(256, 2) void gemm_qkv_bf(const bf16* __restrict__ Aq,
                                                      const bf16* __restrict__ Akv,
                                                      const float* __restrict__ bq,
                                                      const float* __restrict__ bk,
                                                      const float* __restrict__ bv,
                                                      bf16* __restrict__ outQ,
                                                      bf16* __restrict__ outK,
                                                      bf16* __restrict__ outV)
{
    extern __shared__ __align__(16) bf16 smraw[];
    bf16* As = smraw;                 // 3 x 128*72
    bf16* Bs = smraw + 3*9216;        // 3 x 128*72

    const int seg = blockIdx.y >> 2;            // 0=Q 1=K 2=V
    const bf16*  A    = seg ? Akv : Aq;
    const bf16*  W    = g_Wh + (size_t)seg*Cc*Cc;
    const float* bias = (seg == 0) ? bq : (seg == 1) ? bk : bv;
    bf16*        out  = (seg == 0) ? outQ : (seg == 1) ? outK : outV;
    const bool   rope = (seg < 2);
    const int j0 = (blockIdx.y & 3) * 128;

    const int t0 = blockIdx.x * 128;
    const int b  = t0 >> 12;
    const int n0 = t0 & 4095;
    const int tid = threadIdx.x;
    const int lane = tid & 31, wid = tid >> 5;
    const int wm = wid & 1, wn = wid >> 1;
    const int r = lane >> 2, q = lane & 3;
    const int grp = lane >> 3, lr = lane & 7;

    float acc[4][4][4];
#pragma unroll
    for (int i = 0; i < 4; i++)
#pragma unroll
        for (int j = 0; j < 4; j++)
#pragma unroll
            for (int k = 0; k < 4; k++) acc[i][j][k] = 0.f;

#define LOAD_QKV(S, BUF)                                                        \
    {                                                                           \
        bf16* Ad = As + (BUF)*9216;                                             \
        bf16* Bd = Bs + (BUF)*9216;                                             \
        int c0 = (S)*64;                                                        \
        _Pragma("unroll")                                                       \
        for (int u = 0; u < 4; u++) {                                           \
            int flat = u*256 + tid;                                             \
            int m = flat >> 3, kc = flat & 7;                                   \
            CP16(sptr(Ad + m*72 + kc*8),                                        \
                 A + (size_t)(t0+m)*Cc + c0 + kc*8);                            \
            CP16(sptr(Bd + m*72 + kc*8),                                        \
                 W + (size_t)(j0+m)*Cc + c0 + kc*8);                            \
        }                                                                       \
    }

    LOAD_QKV(0, 0); CP_COMMIT();
    LOAD_QKV(1, 1); CP_COMMIT();

#pragma unroll 1
    for (int s = 0; s < 8; s++) {
        if (s < 7) { CP_WAIT(1); } else { CP_WAIT(0); }
        __syncthreads();
        if (s < 6) { LOAD_QKV(s+2, (s+2)%3); CP_COMMIT(); }

        const bf16* Ac = As + (s%3)*9216;
        const bf16* Bc = Bs + (s%3)*9216;
#pragma unroll
        for (int kk = 0; kk < 4; kk++) {
            unsigned af[4][4], bfr[4][2];
#pragma unroll
            for (int i = 0; i < 4; i++) {
                int m  = wm*64 + 16*i + ((grp & 1) ? 8 : 0) + lr;
                int ka = (grp & 2) ? 8 : 0;
                ldsm_x4(af[i][0], af[i][1], af[i][2], af[i][3],
                        sptr(Ac + m*72 + kk*16 + ka));
            }
#pragma unroll
            for (int jg = 0; jg < 2; jg++) {
                int n = wn*32 + jg*16 + ((grp & 2) ? 8 : 0) + lr;
                int ka = (grp & 1) ? 8 : 0;
                ldsm_x4(bfr[jg*2][0], bfr[jg*2][1], bfr[jg*2+1][0], bfr[jg*2+1][1],
                        sptr(Bc + n*72 + kk*16 + ka));
            }
#pragma unroll
            for (int i = 0; i < 4; i++)
#pragma unroll
                for (int j = 0; j < 4; j++)
                    mma_bf16(acc[i][j], af[i], bfr[j]);
        }
    }
#undef LOAD_QKV

    // ---- epilogue: bias (+ RoPE, fp32), store bf16 ----
#pragma unroll
    for (int i = 0; i < 4; i++) {
        int ntok = n0 + wm*64 + 16*i + r;
#pragma unroll
        for (int j = 0; j < 4; j++) {
            int jj = j0 + wn*32 + 8*j + 2*q;
            int hh = jj >> 6;
            int d  = jj & 63;                  // even
            float bv0 = bias[jj], bv1 = bias[jj+1];
#pragma unroll
            for (int half = 0; half < 2; half++) {
                int n = ntok + 8*half;
                float v0 = acc[i][j][2*half+0] + bv0;
                float v1 = acc[i][j][2*half+1] + bv1;
                float x, y;
                if (rope) {
                    int p = (n << 5) + (d >> 1);
                    float sv = g_sin[p], cv = g_cos[p];
                    x = v0*cv - v1*sv;
                    y = v0*sv + v1*cv;
                } else { x = v0; y = v1; }
                *(__nv_bfloat162*)&out[(((size_t)b*NHh + hh)*Nn + n)*Dd + d] =
                    __floats2bfloat162_rn(x, y);
            }
        }
    }
}

// ================= bf16 GEMM (NT): output projection, BK=64 ==================
__global__ __launch_bounds__(256, 2) void gemm_o_bf(const bf16* __restrict__ A,
                                                    const bf16* __restrict__ W,
                                                    const float* __restrict__ bias,
                                                    const float* __restrict__ resid,
                                                    float* __restrict__ out)
{
    extern __shared__ __align__(16) bf16 smraw[];
    bf16* As = smraw;                 // 3 x 128*72
    bf16* Bs = smraw + 3*9216;        // 3 x 128*72

    const int t0 = blockIdx.x * 128;
    const int b  = t0 >> 12;
    const int n0 = t0 & 4095;
    const int j0 = blockIdx.y * 128;
    const int tid = threadIdx.x;
    const int lane = tid & 31, wid = tid >> 5;
    const int wm = wid & 1, wn = wid >> 1;
    const int r = lane >> 2, q = lane & 3;
    const int grp = lane >> 3, lr = lane & 7;

    float acc[4][4][4];
#pragma unroll
    for (int i = 0; i < 4; i++)
#pragma unroll
        for (int j = 0; j < 4; j++)
#pragma unroll
            for (int k = 0; k < 4; k++) acc[i][j][k] = 0.f;

#define LOAD_O(S, BUF)                                                          \
    {                                                                           \
        bf16* Ad = As + (BUF)*9216;                                             \
        bf16* Bd = Bs + (BUF)*9216;                                             \
        int c0 = (S)*64;                                                        \
        _Pragma("unroll")                                                       \
        for (int u = 0; u < 4; u++) {                                           \
            int flat = u*256 + tid;                                             \
            int m = flat >> 3, kc = flat & 7;                                   \
            CP16(sptr(Ad + m*72 + kc*8),                                        \
                 A + (size_t)(t0+m)*Cc + c0 + kc*8);                            \
            CP16(sptr(Bd + m*72 + kc*8),                                        \
                 W + (size_t)(j0+m)*Cc + c0 + kc*8);                            \
        }                                                                       \
    }

    LOAD_O(0, 0); CP_COMMIT();
    LOAD_O(1, 1); CP_COMMIT();

#pragma unroll 1
    for (int s = 0; s < 8; s++) {
        if (s < 7) { CP_WAIT(1); } else { CP_WAIT(0); }
        __syncthreads();
        if (s < 6) { LOAD_O(s+2, (s+2)%3); CP_COMMIT(); }

        const bf16* Ac = As + (s%3)*9216;
        const bf16* Bc = Bs + (s%3)*9216;
#pragma unroll
        for (int kk = 0; kk < 4; kk++) {
            unsigned af[4][4], bfr[4][2];
#pragma unroll
            for (int i = 0; i < 4; i++) {
                int m  = wm*64 + 16*i + ((grp & 1) ? 8 : 0) + lr;
                int ka = (grp & 2) ? 8 : 0;
                ldsm_x4(af[i][0], af[i][1], af[i][2], af[i][3],
                        sptr(Ac + m*72 + kk*16 + ka));
            }
#pragma unroll
            for (int jg = 0; jg < 2; jg++) {
                int n = wn*32 + jg*16 + ((grp & 2) ? 8 : 0) + lr;
                int ka = (grp & 1) ? 8 : 0;
                ldsm_x4(bfr[jg*2][0], bfr[jg*2][1], bfr[jg*2+1][0], bfr[jg*2+1][1],
                        sptr(Bc + n*72 + kk*16 + ka));
            }
#pragma unroll
            for (int i = 0; i < 4; i++)
#pragma unroll
                for (int j = 0; j < 4; j++)
                    mma_bf16(acc[i][j], af[i], bfr[j]);
        }
    }
#undef LOAD_O

    // ---- epilogue: bias + residual (fp32), write (B,C,N) ----
#pragma unroll
    for (int j = 0; j < 4; j++) {
        int jj0 = j0 + wn*32 + 8*j + 2*q;
#pragma unroll
        for (int col = 0; col < 2; col++) {
            int jj = jj0 + col;
            float bj = bias[jj];
            size_t rowbase = ((size_t)b*Cc + jj)*Nn;
#pragma unroll
            for (int i = 0; i < 4; i++) {
#pragma unroll
                for (int half = 0; half < 2; half++) {
                    int n = n0 + wm*64 + 16*i + r + 8*half;
                    size_t o = rowbase + n;
                    out[o] = acc[i][j][2*half + col] + bj + resid[o];
                }
            }
        }
    }
}

// ---------------- windowed attention (bf16 mma), 1 block per (head, window) --
__global__ __launch_bounds__(128) void attn_bf()
{
    __shared__ __align__(16) bf16 Qs[64*72];
    __shared__ __align__(16) bf16 Ks[64*72];
    __shared__ __align__(16) bf16 Vs[64*72];

    const int bx  = blockIdx.x;     // 0..4095
    const int h   = bx >> 9;
    const int win = bx & 511;
    const int b   = win >> 6;
    const int w   = win & 63;
    const int wy  = w >> 3, wx = w & 7;
    const int tid = threadIdx.x;
    const int lane = tid & 31, wid = tid >> 5;
    const int grp = lane >> 3, lr = lane & 7;

    {
        int t  = tid & 63;
        int c2 = tid >> 6;
        int n_t = ((wy*8 + (t >> 3)) << 6) + wx*8 + (t & 7);
        size_t base = (((size_t)b*NHh + h)*Nn + n_t)*Dd;
#pragma unroll
        for (int u = 0; u < 4; u++) {
            int off = c2*32 + u*8;
            uint4 qv = *(const uint4*)((const char*)g_Qh + (base + off)*2);
            uint4 kv = *(const uint4*)((const char*)g_Kh + (base + off)*2);
            uint4 vv = *(const uint4*)((const char*)g_Vh + (base + off)*2);
            *(uint4*)((char*)Qs + (t*72 + off)*2) = qv;
            *(uint4*)((char*)Ks + (t*72 + off)*2) = kv;
            *(uint4*)((char*)Vs + (t*72 + off)*2) = vv;
        }
    }
    __syncthreads();

    const int m0 = wid * 16;

    unsigned af[4][4];
#pragma unroll
    for (int kk = 0; kk < 4; kk++) {
        int m  = m0 + ((grp & 1) ? 8 : 0) + lr;
        int ka = (grp & 2) ? 8 : 0;
        ldsm_x4(af[kk][0], af[kk][1], af[kk][2], af[kk][3],
                sptr(Qs + m*72 + kk*16 + ka));
    }

    float s[8][4];
#pragma unroll
    for (int j = 0; j < 8; j++)
#pragma unroll
        for (int c = 0; c < 4; c++) s[j][c] = 0.f;

#pragma unroll
    for (int kk = 0; kk < 4; kk++) {
        unsigned bfr[8][2];
#pragma unroll
        for (int jg = 0; jg < 4; jg++) {
            int n  = jg*16 + ((grp & 2) ? 8 : 0) + lr;
            int ka = (grp & 1) ? 8 : 0;
            ldsm_x4(bfr[jg*2][0], bfr[jg*2][1], bfr[jg*2+1][0], bfr[jg*2+1][1],
                    sptr(Ks + n*72 + kk*16 + ka));
        }
#pragma unroll
        for (int j = 0; j < 8; j++)
            mma_bf16(s[j], af[kk], bfr[j]);
    }

    const float* bh = g_bias + (h << 12);
    const int row0 = m0 + (lane >> 2);
    const int col0 = 2 * (lane & 3);
    float mx0 = -1e30f, mx1 = -1e30f;
#pragma unroll
    for (int j = 0; j < 8; j++) {
        float2 b0 = *(const float2*)(bh + row0*64 + 8*j + col0);
        float2 b1 = *(const float2*)(bh + (row0+8)*64 + 8*j + col0);
        s[j][0] = fmaf(s[j][0], 0.125f, b0.x);
        s[j][1] = fmaf(s[j][1], 0.125f, b0.y);
        s[j][2] = fmaf(s[j][2], 0.125f, b1.x);
        s[j][3] = fmaf(s[j][3], 0.125f, b1.y);
        mx0 = fmaxf(mx0, fmaxf(s[j][0], s[j][1]));
        mx1 = fmaxf(mx1, fmaxf(s[j][2], s[j][3]));
    }
    mx0 = fmaxf(mx0, __shfl_xor_sync(0xffffffffu, mx0, 1));
    mx0 = fmaxf(mx0, __shfl_xor_sync(0xffffffffu, mx0, 2));
    mx1 = fmaxf(mx1, __shfl_xor_sync(0xffffffffu, mx1, 1));
    mx1 = fmaxf(mx1, __shfl_xor_sync(0xffffffffu, mx1, 2));

    float sum0 = 0.f, sum1 = 0.f;
#pragma unroll
    for (int j = 0; j < 8; j++) {
        s[j][0] = __expf(s[j][0] - mx0);
        s[j][1] = __expf(s[j][1] - mx0);
        s[j][2] = __expf(s[j][2] - mx1);
        s[j][3] = __expf(s[j][3] - mx1);
        sum0 += s[j][0] + s[j][1];
        sum1 += s[j][2] + s[j][3];
    }
    sum0 += __shfl_xor_sync(0xffffffffu, sum0, 1);
    sum0 += __shfl_xor_sync(0xffffffffu, sum0, 2);
    sum1 += __shfl_xor_sync(0xffffffffu, sum1, 1);
    sum1 += __shfl_xor_sync(0xffffffffu, sum1, 2);
    float inv0 = 1.f / sum0, inv1 = 1.f / sum1;

    float o[8][4];
#pragma unroll
    for (int j = 0; j < 8; j++)
#pragma unroll
        for (int c = 0; c < 4; c++) o[j][c] = 0.f;

#pragma unroll
    for (int kk = 0; kk < 4; kk++) {
        unsigned pa[4];
        pa[0] = packbf(s[2*kk  ][0], s[2*kk  ][1]);
        pa[1] = packbf(s[2*kk  ][2], s[2*kk  ][3]);
        pa[2] = packbf(s[2*kk+1][0], s[2*kk+1][1]);
        pa[3] = packbf(s[2*kk+1][2], s[2*kk+1][3]);
        unsigned vb[8][2];
#pragma unroll
        for (int jg = 0; jg < 4; jg++) {
            int rowk = kk*16 + ((grp & 1) ? 8 : 0) + lr;
            int cold = jg*16 + ((grp & 2) ? 8 : 0);
            ldsm_x4t(vb[jg*2][0], vb[jg*2][1], vb[jg*2+1][0], vb[jg*2+1][1],
                     sptr(Vs + rowk*72 + cold));
        }
#pragma unroll
        for (int j = 0; j < 8; j++)
            mma_bf16(o[j], pa, vb[j]);
    }

    {
        int tA = row0, tB = row0 + 8;
        int nA = ((wy*8 + (tA >> 3)) << 6) + wx*8 + (tA & 7);
        int nB = ((wy*8 + (tB >> 3)) << 6) + wx*8 + (tB & 7);
        size_t baseA = ((size_t)b*Nn + nA)*Cc + (h << 6);
        size_t baseB = ((size_t)b*Nn + nB)*Cc + (h << 6);
#pragma unroll
        for (int j = 0; j < 8; j++) {
            int d = 8*j + col0;
            *(__nv_bfloat162*)&g_AOh[baseA + d] =
                __floats2bfloat162_rn(o[j][0]*inv0, o[j][1]*inv0);
            *(__nv_bfloat162*)&g_AOh[baseB + d] =
                __floats2bfloat162_rn(o[j][2]*inv1, o[j][3]*inv1);
        }
    }
}

// ---------------- host side ----------------
extern "C" void kernel_launch(void* const* d_in, const int* in_sizes, int n_in,
                              void* d_out, int out_size)
{
    const float* q    = (const float*)d_in[0];
    const float* kv   = (const float*)d_in[1];
    const float* gq   = (const float*)d_in[2];
    const float* bqln = (const float*)d_in[3];
    const float* gkv  = (const float*)d_in[4];
    const float* bkvln= (const float*)d_in[5];
    const float* Wq   = (const float*)d_in[6];
    const float* bq   = (const float*)d_in[7];
    const float* Wk   = (const float*)d_in[8];
    const float* bk   = (const float*)d_in[9];
    const float* Wv   = (const float*)d_in[10];
    const float* bv   = (const float*)d_in[11];
    const float* Wo   = (const float*)d_in[12];
    const float* bo   = (const float*)d_in[13];
    const float* tbl  = (const float*)d_in[14];
    float* out = (float*)d_out;

    void* p;
    cudaGetSymbolAddress(&p, g_qn);   float* qn   = (float*)p;
    cudaGetSymbolAddress(&p, g_qnt);  bf16* qnt   = (bf16*)p;
    cudaGetSymbolAddress(&p, g_kvnt); bf16* kvnt  = (bf16*)p;
    cudaGetSymbolAddress(&p, g_Wh);   bf16* Wh    = (bf16*)p;
    cudaGetSymbolAddress(&p, g_Qh);   bf16* Qb    = (bf16*)p;
    cudaGetSymbolAddress(&p, g_Kh);   bf16* Kb    = (bf16*)p;
    cudaGetSymbolAddress(&p, g_Vh);   bf16* Vb    = (bf16*)p;
    cudaGetSymbolAddress(&p, g_AOh);  bf16* AO    = (bf16*)p;

    const int SMEM_LN = (512*33 + 512 + 64) * 4;     // 69888 B
    const int SMEM_G  = (6*9216) * 2;                // 110592 B
    static int smem_set = 0;
    if (!smem_set) {
        cudaFuncSetAttribute(ln_kernel<true>,  cudaFuncAttributeMaxDynamicSharedMemorySize, SMEM_LN);
        cudaFuncSetAttribute(ln_kernel<false>, cudaFuncAttributeMaxDynamicSharedMemorySize, SMEM_LN);
        cudaFuncSetAttribute(gemm_qkv_bf,      cudaFuncAttributeMaxDynamicSharedMemorySize, SMEM_G);
        cudaFuncSetAttribute(gemm_o_bf,        cudaFuncAttributeMaxDynamicSharedMemorySize, SMEM_G);
        smem_set = 1;
    }

    // 0: weight cvt + rope + bias tables (one launch)
    prep_kernel<<<1664, 256>>>(Wq, Wk, Wv, Wo, tbl);

    // 1,2: layernorms (token-major bf16 out; q also fp32 channel-major)
    ln_kernel<true ><<<1024, 256, SMEM_LN>>>(q,  gq,  bqln,  qn, qnt);
    ln_kernel<false><<<1024, 256, SMEM_LN>>>(kv, gkv, bkvln, qn, kvnt);

    // 3: merged Q/K/V projections (rope fused for Q and K)
    gemm_qkv_bf<<<dim3(256, 12), 256, SMEM_G>>>(qnt, kvnt, bq, bk, bv, Qb, Kb, Vb);

    // 4: windowed attention
    attn_bf<<<NHh * Bb * 64, 128>>>();

    // 5: output projection + bias + residual -> (B,C,H,W)
    gemm_o_bf<<<dim3(256, 4), 256, SMEM_G>>>(AO, Wh + 3*Cc*Cc, bo, qn, out);
}